// round 1
// baseline (speedup 1.0000x reference)
#include <cuda_runtime.h>
#include <math.h>

// Problem constants (fixed by setup_inputs)
#define NB   4
#define CM   128     // channels per modality
#define CTOT 256
#define NO   128     // output channels
#define NH   64
#define NW   64
#define NHW  4096
#define OFFC 54

// -------- device scratch (no allocations allowed) --------
__device__ float g_off [NB*OFFC*NHW];        // offset-conv output (mask channels pre-sigmoided)
__device__ float g_wT  [2*9*128*128];        // dconv_w transposed: [g][k][c][o]
__device__ float g_wT1 [CTOT*9*OFFC];        // off_w transposed:   [ci][kk][co]
__device__ float g_wT2 [NO*9*NO];            // conv2_w transposed: [ci][kk][co]
__device__ float g_out1[NB*NO*NHW];          // raw deform-conv output (pre-BN1)
__device__ float g_out2[NB*NO*NHW];          // raw conv2 output (pre-BN2)
__device__ float g_sum1[NO], g_sq1[NO], g_sum2[NO], g_sq2[NO];
__device__ float g_scale1[NO], g_shift1[NO], g_scale2[NO], g_shift2[NO];

// -------- K0: zero BN stats --------
__global__ void k_zero() {
    int t = threadIdx.x;
    if (t < NO) { g_sum1[t] = 0.f; g_sq1[t] = 0.f; g_sum2[t] = 0.f; g_sq2[t] = 0.f; }
}

// -------- K0b: transpose all weights once per launch (coalesced writes) --------
// sizes: wT 294912, wT1 124416, wT2 147456  -> total 566784 = 2214*256
__global__ void k_transpose(const float* __restrict__ dconv_w,
                            const float* __restrict__ off_w,
                            const float* __restrict__ conv2_w) {
    int idx = blockIdx.x * 256 + threadIdx.x;
    if (idx < 294912) {
        int o = idx & 127; int c = (idx >> 7) & 127; int gk = idx >> 14;
        int k = gk % 9; int g = gk / 9;
        g_wT[idx] = dconv_w[(o * 256 + g * 128 + c) * 9 + k];
    } else if (idx < 294912 + 124416) {
        int j = idx - 294912;
        int co = j % 54; int a = j / 54; int ci = a / 9; int kk = a % 9;
        g_wT1[j] = off_w[(co * 256 + ci) * 9 + kk];
    } else if (idx < 294912 + 124416 + 147456) {
        int j = idx - 419328;
        int co = j & 127; int a = j >> 7; int ci = a / 9; int kk = a % 9;
        g_wT2[j] = conv2_w[(co * 128 + ci) * 9 + kk];
    }
}

// -------- K1: offset conv3x3  (Cin=256 -> 54), SAME padding, bias, sigmoid on mask chans --------
// block = (b,h) row, 256 blocks. threads: w = tid&63, q = tid>>6. co = q + 4*j (j<14).
__global__ __launch_bounds__(256) void k_offconv(const float* __restrict__ xv,
                                                 const float* __restrict__ xi,
                                                 const float* __restrict__ off_b) {
    int b = blockIdx.x >> 6; int h = blockIdx.x & 63;
    int tid = threadIdx.x; int w = tid & 63; int q = tid >> 6;

    __shared__ float sx[16 * 3 * 64];       // 12 KB  [ci][r][w]
    __shared__ float sw[16 * 9 * 56];       // 31.5 KB [ci][kk][co-padded-56]

    float acc[14];
#pragma unroll
    for (int j = 0; j < 14; j++) acc[j] = 0.f;

    for (int ch = 0; ch < 16; ch++) {
        int ci0 = ch * 16;
        __syncthreads();
        // zero the 2-wide pad region (co 54,55) -- disjoint from valid region, no race
        for (int i = tid; i < 16 * 9 * 2; i += 256) {
            int a = i >> 1;
            sw[a * 56 + 54 + (i & 1)] = 0.f;
        }
        // load valid weights: g_wT1 is [ci][kk][co] contiguous => coalesced
        for (int i = tid; i < 16 * 9 * 54; i += 256) {
            int a = i / 54; int co = i - a * 54;
            sw[a * 56 + co] = g_wT1[ci0 * (9 * 54) + i];
        }
        // load x tile: 16 channels x 3 rows x 64 cols, coalesced
        for (int i = tid; i < 16 * 3 * 64; i += 256) {
            int ci = i / 192; int r = (i >> 6) % 3; int wc = i & 63;
            int hh = h - 1 + r;
            float v = 0.f;
            if (hh >= 0 && hh < 64) {
                int c = ci0 + ci;
                v = (c < 128) ? xv[((size_t)(b * 128 + c) * 64 + hh) * 64 + wc]
                              : xi[((size_t)(b * 128 + (c - 128)) * 64 + hh) * 64 + wc];
            }
            sx[i] = v;
        }
        __syncthreads();

        for (int ci = 0; ci < 16; ci++) {
#pragma unroll
            for (int kk = 0; kk < 9; kk++) {
                int ky = kk / 3, kx = kk % 3;
                int ww = w + kx - 1;
                float xval = (ww >= 0 && ww < 64) ? sx[ci * 192 + ky * 64 + ww] : 0.f;
                const float* wrow = &sw[(ci * 9 + kk) * 56 + q];
#pragma unroll
                for (int j = 0; j < 14; j++) acc[j] += xval * wrow[4 * j];
            }
        }
    }

#pragma unroll
    for (int j = 0; j < 14; j++) {
        int co = q + 4 * j;
        if (co < 54) {
            float v = acc[j] + off_b[co];
            if (co >= 36) v = 1.f / (1.f + expf(-v));   // sigmoid for mask channels
            g_off[((size_t)(b * 54 + co) * 64 + h) * 64 + w] = v;
        }
    }
}

// -------- K2: deform-sample + grouped 2304-deep GEMM -> g_out1 + BN1 stats --------
// block = (b,h) row (256 blocks). thread: og=tid>>4 (8 o's), pw=tid&15 (4 w's). acc[8][4].
__global__ __launch_bounds__(256) void k_deform(const float* __restrict__ xv,
                                                const float* __restrict__ xi) {
    int b = blockIdx.x >> 6; int h = blockIdx.x & 63;
    int tid = threadIdx.x;
    int og = tid >> 4; int pw = tid & 15;

    __shared__ float sv [32 * 64];     // 8 KB   sampled vals [c][w]
    __shared__ float swt[32 * 128];    // 16 KB  weights      [c][o]
    __shared__ int   si[4][64];        // bilinear gather indices per w
    __shared__ float sb[4][64];        // bilinear weights (mask folded in)

    float acc[8][4];
#pragma unroll
    for (int oi = 0; oi < 8; oi++)
#pragma unroll
        for (int pi = 0; pi < 4; pi++) acc[oi][pi] = 0.f;

    for (int gk = 0; gk < 18; gk++) {
        int g = gk / 9, k = gk - g * 9;
        int ky = k / 3 - 1, kx = (k % 3) - 1;
        __syncthreads();
        if (tid < 64) {
            int w = tid;
            const float* offp = g_off + (size_t)b * 54 * NHW + h * 64 + w;
            float dy = offp[(size_t)(g * 18 + 2 * k) * NHW];
            float dx = offp[(size_t)(g * 18 + 2 * k + 1) * NHW];
            float m  = offp[(size_t)(36 + g * 9 + k) * NHW];
            float py = dy + (float)(h + ky);
            float px = dx + (float)(w + kx);
            float fy = floorf(py), fx = floorf(px);
            float ly = py - fy,   lx = px - fx;
            int y0 = (int)fy, x0 = (int)fx;
            int y1 = y0 + 1,  x1 = x0 + 1;
            float o00 = (y0 >= 0 && y0 < 64 && x0 >= 0 && x0 < 64) ? 1.f : 0.f;
            float o01 = (y0 >= 0 && y0 < 64 && x1 >= 0 && x1 < 64) ? 1.f : 0.f;
            float o10 = (y1 >= 0 && y1 < 64 && x0 >= 0 && x0 < 64) ? 1.f : 0.f;
            float o11 = (y1 >= 0 && y1 < 64 && x1 >= 0 && x1 < 64) ? 1.f : 0.f;
            int cy0 = min(max(y0, 0), 63), cx0 = min(max(x0, 0), 63);
            int cy1 = min(max(y1, 0), 63), cx1 = min(max(x1, 0), 63);
            si[0][w] = cy0 * 64 + cx0;  si[1][w] = cy0 * 64 + cx1;
            si[2][w] = cy1 * 64 + cx0;  si[3][w] = cy1 * 64 + cx1;
            sb[0][w] = (1.f - ly) * (1.f - lx) * o00 * m;
            sb[1][w] = (1.f - ly) * lx         * o01 * m;
            sb[2][w] = ly * (1.f - lx)         * o10 * m;
            sb[3][w] = ly * lx                 * o11 * m;
        }
        __syncthreads();

        const float* xbase = (g == 0 ? xv : xi) + (size_t)b * 128 * NHW;
        for (int cc = 0; cc < 4; cc++) {
            // stage weight slab [32c][128o] (contiguous in g_wT -> coalesced)
            const float* wp = g_wT + ((size_t)(g * 9 + k) * 128 + cc * 32) * 128;
#pragma unroll
            for (int i = 0; i < 16; i++) swt[tid + i * 256] = wp[tid + i * 256];
            // gather sampled values [32c][64w]
#pragma unroll
            for (int i = 0; i < 8; i++) {
                int lin = tid + i * 256;
                int c = lin >> 6, pos = lin & 63;
                const float* xp = xbase + (size_t)(cc * 32 + c) * NHW;
                sv[lin] = sb[0][pos] * __ldg(xp + si[0][pos])
                        + sb[1][pos] * __ldg(xp + si[1][pos])
                        + sb[2][pos] * __ldg(xp + si[2][pos])
                        + sb[3][pos] * __ldg(xp + si[3][pos]);
            }
            __syncthreads();
            // 8o x 4w register-tile GEMM over the 32-channel chunk
#pragma unroll
            for (int c = 0; c < 32; c++) {
                float4 xa = *(const float4*)&sv[c * 64 + pw * 4];
                float4 wa = *(const float4*)&swt[c * 128 + og * 8];
                float4 wb = *(const float4*)&swt[c * 128 + og * 8 + 4];
                float xs[4] = {xa.x, xa.y, xa.z, xa.w};
                float ws[8] = {wa.x, wa.y, wa.z, wa.w, wb.x, wb.y, wb.z, wb.w};
#pragma unroll
                for (int oi = 0; oi < 8; oi++)
#pragma unroll
                    for (int pi = 0; pi < 4; pi++) acc[oi][pi] += ws[oi] * xs[pi];
            }
            __syncthreads();
        }
    }

    // epilogue: store raw + BN1 statistics (warp-segment reduce then atomics)
    float* outp = g_out1 + ((size_t)(b * 128) * 64 + h) * 64;
#pragma unroll
    for (int oi = 0; oi < 8; oi++) {
        int o = og * 8 + oi;
        float4 v4 = make_float4(acc[oi][0], acc[oi][1], acc[oi][2], acc[oi][3]);
        *(float4*)(outp + (size_t)o * NHW + pw * 4) = v4;
        float s  = acc[oi][0] + acc[oi][1] + acc[oi][2] + acc[oi][3];
        float sq = acc[oi][0] * acc[oi][0] + acc[oi][1] * acc[oi][1]
                 + acc[oi][2] * acc[oi][2] + acc[oi][3] * acc[oi][3];
#pragma unroll
        for (int off = 8; off; off >>= 1) {
            s  += __shfl_down_sync(0xffffffffu, s,  off, 16);
            sq += __shfl_down_sync(0xffffffffu, sq, off, 16);
        }
        if (pw == 0) { atomicAdd(&g_sum1[o], s); atomicAdd(&g_sq1[o], sq); }
    }
}

// -------- K3/K5: fold BN stats into per-channel scale/shift --------
__global__ void k_bn1(const float* __restrict__ gamma, const float* __restrict__ beta) {
    int c = threadIdx.x;
    float m  = g_sum1[c] * (1.f / 16384.f);
    float vv = g_sq1[c]  * (1.f / 16384.f) - m * m;
    float sc = gamma[c] * rsqrtf(vv + 1e-5f);
    g_scale1[c] = sc;
    g_shift1[c] = beta[c] - m * sc;
}
__global__ void k_bn2(const float* __restrict__ gamma, const float* __restrict__ beta) {
    int c = threadIdx.x;
    float m  = g_sum2[c] * (1.f / 16384.f);
    float vv = g_sq2[c]  * (1.f / 16384.f) - m * m;
    float sc = gamma[c] * rsqrtf(vv + 1e-5f);
    g_scale2[c] = sc;
    g_shift2[c] = beta[c] - m * sc;
}

// -------- K4: conv3x3 (128->128) with BN1+ReLU applied at load; writes raw + BN2 stats --------
// block = (b,h) row (256 blocks). threads: w = tid&63, q = tid>>6. co = q*32 + j (32 accs).
__global__ __launch_bounds__(256) void k_conv2() {
    int b = blockIdx.x >> 6; int h = blockIdx.x & 63;
    int tid = threadIdx.x; int w = tid & 63; int q = tid >> 6;

    __shared__ float sx[8 * 3 * 64];     // 6 KB
    __shared__ float sw[8 * 9 * 128];    // 36 KB  [ci][kk][co]

    float acc[32];
#pragma unroll
    for (int j = 0; j < 32; j++) acc[j] = 0.f;

    for (int ch = 0; ch < 16; ch++) {
        int ci0 = ch * 8;
        __syncthreads();
        for (int i = tid; i < 8 * 9 * 128; i += 256) sw[i] = g_wT2[ci0 * 1152 + i];
        for (int i = tid; i < 8 * 3 * 64; i += 256) {
            int ci = i / 192; int r = (i >> 6) % 3; int wc = i & 63;
            int hh = h - 1 + r; int c = ci0 + ci;
            float v = 0.f;
            if (hh >= 0 && hh < 64) {
                float raw = g_out1[((size_t)(b * 128 + c) * 64 + hh) * 64 + wc];
                v = fmaxf(0.f, raw * g_scale1[c] + g_shift1[c]);
            }
            sx[i] = v;
        }
        __syncthreads();

        for (int ci = 0; ci < 8; ci++) {
#pragma unroll
            for (int kk = 0; kk < 9; kk++) {
                int ky = kk / 3, kx = kk % 3;
                int ww = w + kx - 1;
                float xval = (ww >= 0 && ww < 64) ? sx[ci * 192 + ky * 64 + ww] : 0.f;
                const float4* wrow = (const float4*)&sw[(ci * 9 + kk) * 128 + q * 32];
#pragma unroll
                for (int j4 = 0; j4 < 8; j4++) {
                    float4 wv = wrow[j4];
                    acc[j4 * 4 + 0] += xval * wv.x;
                    acc[j4 * 4 + 1] += xval * wv.y;
                    acc[j4 * 4 + 2] += xval * wv.z;
                    acc[j4 * 4 + 3] += xval * wv.w;
                }
            }
        }
    }

#pragma unroll
    for (int j = 0; j < 32; j++) {
        int co = q * 32 + j;
        float v = acc[j];
        g_out2[((size_t)(b * 128 + co) * 64 + h) * 64 + w] = v;
        float s = v, sq = v * v;
#pragma unroll
        for (int off = 16; off; off >>= 1) {
            s  += __shfl_down_sync(0xffffffffu, s,  off);
            sq += __shfl_down_sync(0xffffffffu, sq, off);
        }
        if ((tid & 31) == 0) { atomicAdd(&g_sum2[co], s); atomicAdd(&g_sq2[co], sq); }
    }
}

// -------- K6: final BN2 + ReLU elementwise into d_out --------
__global__ void k_final(float* __restrict__ out) {
    int idx = blockIdx.x * 256 + threadIdx.x;   // 2097152 total
    float v = g_out2[idx];
    int c = (idx >> 12) & 127;
    out[idx] = fmaxf(0.f, v * g_scale2[c] + g_shift2[c]);
}

// -------- host launcher (graph-capturable: kernel launches only, default stream) --------
extern "C" void kernel_launch(void* const* d_in, const int* in_sizes, int n_in,
                              void* d_out, int out_size) {
    const float* input_v = (const float*)d_in[0];
    const float* input_i = (const float*)d_in[1];
    const float* off_w   = (const float*)d_in[2];
    const float* off_b   = (const float*)d_in[3];
    const float* dconv_w = (const float*)d_in[4];
    const float* bn1_g   = (const float*)d_in[5];
    const float* bn1_b   = (const float*)d_in[6];
    const float* conv2_w = (const float*)d_in[7];
    const float* bn2_g   = (const float*)d_in[8];
    const float* bn2_b   = (const float*)d_in[9];
    float* out = (float*)d_out;

    k_zero<<<1, 128>>>();
    k_transpose<<<2214, 256>>>(dconv_w, off_w, conv2_w);
    k_offconv<<<NB * NH, 256>>>(input_v, input_i, off_b);
    k_deform<<<NB * NH, 256>>>(input_v, input_i);
    k_bn1<<<1, 128>>>(bn1_g, bn1_b);
    k_conv2<<<NB * NH, 256>>>();
    k_bn2<<<1, 128>>>(bn2_g, bn2_b);
    k_final<<<8192, 256>>>(out);
}

// round 2
// speedup vs baseline: 1.1844x; 1.1844x over previous
#include <cuda_runtime.h>
#include <math.h>

// Problem constants (fixed by setup_inputs)
#define NB   4
#define CM   128
#define CTOT 256
#define NO   128
#define NH   64
#define NW   64
#define NHW  4096
#define OFFC 54

// ---- packed f32x2 helpers (Blackwell PTX-only FFMA2 path) ----
#define FFMA2(d, a, b) asm("fma.rn.f32x2 %0, %1, %2, %0;" : "+l"(d) : "l"(a), "l"(b))
__device__ __forceinline__ unsigned long long pack2b(float x) {
    unsigned long long r; asm("mov.b64 %0, {%1, %1};" : "=l"(r) : "f"(x)); return r;
}
__device__ __forceinline__ float2 unpack2(unsigned long long v) {
    float2 f; asm("mov.b64 {%0, %1}, %2;" : "=f"(f.x), "=f"(f.y) : "l"(v)); return f;
}

// -------- device scratch (no allocations allowed) --------
__device__ float g_off [NB*OFFC*NHW];
__device__ float g_wT  [2*9*128*128];        // dconv_w transposed: [g][k][c][o]
__device__ float g_wT1 [CTOT*9*OFFC];        // off_w transposed:   [ci][kk][co]
__device__ float g_wT2 [NO*9*NO];            // conv2_w transposed: [ci][kk][co]
__device__ float g_out1[NB*NO*NHW];
__device__ float g_out2[NB*NO*NHW];
__device__ float g_sum1[NO], g_sq1[NO], g_sum2[NO], g_sq2[NO];
__device__ float g_scale1[NO], g_shift1[NO], g_scale2[NO], g_shift2[NO];

// -------- K0: transpose all weights + zero BN stats --------
__global__ void k_transpose(const float* __restrict__ dconv_w,
                            const float* __restrict__ off_w,
                            const float* __restrict__ conv2_w) {
    int idx = blockIdx.x * 256 + threadIdx.x;
    if (idx < 128) { g_sum1[idx] = 0.f; g_sq1[idx] = 0.f; g_sum2[idx] = 0.f; g_sq2[idx] = 0.f; }
    if (idx < 294912) {
        int o = idx & 127; int c = (idx >> 7) & 127; int gk = idx >> 14;
        int k = gk % 9; int g = gk / 9;
        g_wT[idx] = dconv_w[(o * 256 + g * 128 + c) * 9 + k];
    } else if (idx < 294912 + 124416) {
        int j = idx - 294912;
        int co = j % 54; int a = j / 54; int ci = a / 9; int kk = a % 9;
        g_wT1[j] = off_w[(co * 256 + ci) * 9 + kk];
    } else if (idx < 294912 + 124416 + 147456) {
        int j = idx - 419328;
        int co = j & 127; int a = j >> 7; int ci = a / 9; int kk = a % 9;
        g_wT2[j] = conv2_w[(co * 128 + ci) * 9 + kk];
    }
}

// -------- K1: offset conv3x3 (256 -> 54) + bias + sigmoid on mask chans --------
// block=(b,h). w=tid&63, q=tid>>6. weights staged as [ci*9+kk][q][16] so output
// pairs are smem-contiguous for FFMA2.
__global__ __launch_bounds__(256) void k_offconv(const float* __restrict__ xv,
                                                 const float* __restrict__ xi,
                                                 const float* __restrict__ off_b) {
    int b = blockIdx.x >> 6; int h = blockIdx.x & 63;
    int tid = threadIdx.x; int w = tid & 63; int q = tid >> 6;

    __shared__ float sx[16 * 3 * 64];          // 12 KB   [ci][r][w]
    __shared__ float sw[16 * 9 * 4 * 16];      // 36 KB   [a][q][j(16)]

    unsigned long long accp[8];
#pragma unroll
    for (int p = 0; p < 8; p++) accp[p] = 0ull;

    for (int ch = 0; ch < 16; ch++) {
        int ci0 = ch * 16;
        __syncthreads();
        // zero pad slots j=14,15 for every (a,q)  (disjoint from valid writes)
        for (int i = tid; i < 16 * 9 * 4 * 2; i += 256) {
            int j = 14 + (i & 1); int aq = i >> 1;
            sw[aq * 16 + j] = 0.f;
        }
        // valid weights: g_wT1 [ci][kk][co] contiguous reads
        for (int i = tid; i < 16 * 9 * 54; i += 256) {
            int a = i / 54; int co = i - a * 54;
            sw[(a * 4 + (co & 3)) * 16 + (co >> 2)] = g_wT1[ci0 * (9 * 54) + i];
        }
        // x tile
        for (int i = tid; i < 16 * 3 * 64; i += 256) {
            int ci = i / 192; int r = (i >> 6) % 3; int wc = i & 63;
            int hh = h - 1 + r;
            float v = 0.f;
            if (hh >= 0 && hh < 64) {
                int c = ci0 + ci;
                v = (c < 128) ? xv[((size_t)(b * 128 + c) * 64 + hh) * 64 + wc]
                              : xi[((size_t)(b * 128 + (c - 128)) * 64 + hh) * 64 + wc];
            }
            sx[i] = v;
        }
        __syncthreads();

        for (int ci = 0; ci < 16; ci++) {
#pragma unroll
            for (int kk = 0; kk < 9; kk++) {
                int ky = kk / 3, kx = kk % 3;
                int ww = w + kx - 1;
                float xval = (ww >= 0 && ww < 64) ? sx[ci * 192 + ky * 64 + ww] : 0.f;
                unsigned long long xb = pack2b(xval);
                const ulonglong2* wrow = (const ulonglong2*)&sw[((ci * 9 + kk) * 4 + q) * 16];
#pragma unroll
                for (int j4 = 0; j4 < 4; j4++) {
                    ulonglong2 wv = wrow[j4];
                    FFMA2(accp[2 * j4],     wv.x, xb);
                    FFMA2(accp[2 * j4 + 1], wv.y, xb);
                }
            }
        }
    }

#pragma unroll
    for (int p = 0; p < 8; p++) {
        float2 f2 = unpack2(accp[p]);
        int j0 = (p >> 1) * 4 + (p & 1) * 2;
#pragma unroll
        for (int s = 0; s < 2; s++) {
            int j = j0 + s;
            int co = q + 4 * j;
            if (co < 54) {
                float v = (s == 0 ? f2.x : f2.y) + off_b[co];
                if (co >= 36) v = 1.f / (1.f + expf(-v));
                g_off[((size_t)(b * 54 + co) * 64 + h) * 64 + w] = v;
            }
        }
    }
}

// -------- K2: deform-sample + grouped 2304-deep GEMM -> g_out1 + BN1 stats --------
// block=(b,h). og=tid>>4 (8 o's as 4 pairs), pw=tid&15 (4 w's).
__global__ __launch_bounds__(256) void k_deform(const float* __restrict__ xv,
                                                const float* __restrict__ xi) {
    int b = blockIdx.x >> 6; int h = blockIdx.x & 63;
    int tid = threadIdx.x;
    int og = tid >> 4; int pw = tid & 15;

    __shared__ float sv [32 * 64];     // 8 KB
    __shared__ float swt[32 * 128];    // 16 KB
    __shared__ int   si[4][64];
    __shared__ float sb[4][64];

    unsigned long long accp[4][4];     // [o-pair][w]
#pragma unroll
    for (int op = 0; op < 4; op++)
#pragma unroll
        for (int pi = 0; pi < 4; pi++) accp[op][pi] = 0ull;

    for (int gk = 0; gk < 18; gk++) {
        int g = gk / 9, k = gk - g * 9;
        int ky = k / 3 - 1, kx = (k % 3) - 1;
        __syncthreads();
        if (tid < 64) {
            int w = tid;
            const float* offp = g_off + (size_t)b * 54 * NHW + h * 64 + w;
            float dy = offp[(size_t)(g * 18 + 2 * k) * NHW];
            float dx = offp[(size_t)(g * 18 + 2 * k + 1) * NHW];
            float m  = offp[(size_t)(36 + g * 9 + k) * NHW];
            float py = dy + (float)(h + ky);
            float px = dx + (float)(w + kx);
            float fy = floorf(py), fx = floorf(px);
            float ly = py - fy,   lx = px - fx;
            int y0 = (int)fy, x0 = (int)fx;
            int y1 = y0 + 1,  x1 = x0 + 1;
            float o00 = (y0 >= 0 && y0 < 64 && x0 >= 0 && x0 < 64) ? 1.f : 0.f;
            float o01 = (y0 >= 0 && y0 < 64 && x1 >= 0 && x1 < 64) ? 1.f : 0.f;
            float o10 = (y1 >= 0 && y1 < 64 && x0 >= 0 && x0 < 64) ? 1.f : 0.f;
            float o11 = (y1 >= 0 && y1 < 64 && x1 >= 0 && x1 < 64) ? 1.f : 0.f;
            int cy0 = min(max(y0, 0), 63), cx0 = min(max(x0, 0), 63);
            int cy1 = min(max(y1, 0), 63), cx1 = min(max(x1, 0), 63);
            si[0][w] = cy0 * 64 + cx0;  si[1][w] = cy0 * 64 + cx1;
            si[2][w] = cy1 * 64 + cx0;  si[3][w] = cy1 * 64 + cx1;
            sb[0][w] = (1.f - ly) * (1.f - lx) * o00 * m;
            sb[1][w] = (1.f - ly) * lx         * o01 * m;
            sb[2][w] = ly * (1.f - lx)         * o10 * m;
            sb[3][w] = ly * lx                 * o11 * m;
        }
        __syncthreads();

        const float* xbase = (g == 0 ? xv : xi) + (size_t)b * 128 * NHW;
        for (int cc = 0; cc < 4; cc++) {
            const float* wp = g_wT + ((size_t)(g * 9 + k) * 128 + cc * 32) * 128;
#pragma unroll
            for (int i = 0; i < 16; i++) swt[tid + i * 256] = wp[tid + i * 256];
#pragma unroll
            for (int i = 0; i < 8; i++) {
                int lin = tid + i * 256;
                int c = lin >> 6, pos = lin & 63;
                const float* xp = xbase + (size_t)(cc * 32 + c) * NHW;
                sv[lin] = sb[0][pos] * __ldg(xp + si[0][pos])
                        + sb[1][pos] * __ldg(xp + si[1][pos])
                        + sb[2][pos] * __ldg(xp + si[2][pos])
                        + sb[3][pos] * __ldg(xp + si[3][pos]);
            }
            __syncthreads();
#pragma unroll
            for (int c = 0; c < 32; c++) {
                float4 xa = *(const float4*)&sv[c * 64 + pw * 4];
                unsigned long long xp0 = pack2b(xa.x), xp1 = pack2b(xa.y);
                unsigned long long xp2 = pack2b(xa.z), xp3 = pack2b(xa.w);
                ulonglong2 wv0 = *(const ulonglong2*)&swt[c * 128 + og * 8];
                ulonglong2 wv1 = *(const ulonglong2*)&swt[c * 128 + og * 8 + 4];
                FFMA2(accp[0][0], wv0.x, xp0); FFMA2(accp[0][1], wv0.x, xp1);
                FFMA2(accp[0][2], wv0.x, xp2); FFMA2(accp[0][3], wv0.x, xp3);
                FFMA2(accp[1][0], wv0.y, xp0); FFMA2(accp[1][1], wv0.y, xp1);
                FFMA2(accp[1][2], wv0.y, xp2); FFMA2(accp[1][3], wv0.y, xp3);
                FFMA2(accp[2][0], wv1.x, xp0); FFMA2(accp[2][1], wv1.x, xp1);
                FFMA2(accp[2][2], wv1.x, xp2); FFMA2(accp[2][3], wv1.x, xp3);
                FFMA2(accp[3][0], wv1.y, xp0); FFMA2(accp[3][1], wv1.y, xp1);
                FFMA2(accp[3][2], wv1.y, xp2); FFMA2(accp[3][3], wv1.y, xp3);
            }
            __syncthreads();
        }
    }

    // unpack pairs -> acc[8][4]
    float acc[8][4];
#pragma unroll
    for (int op = 0; op < 4; op++)
#pragma unroll
        for (int pi = 0; pi < 4; pi++) {
            float2 f2 = unpack2(accp[op][pi]);
            acc[2 * op][pi]     = f2.x;
            acc[2 * op + 1][pi] = f2.y;
        }

    float* outp = g_out1 + ((size_t)(b * 128) * 64 + h) * 64;
#pragma unroll
    for (int oi = 0; oi < 8; oi++) {
        int o = og * 8 + oi;
        float4 v4 = make_float4(acc[oi][0], acc[oi][1], acc[oi][2], acc[oi][3]);
        *(float4*)(outp + (size_t)o * NHW + pw * 4) = v4;
        float s  = acc[oi][0] + acc[oi][1] + acc[oi][2] + acc[oi][3];
        float sq = acc[oi][0] * acc[oi][0] + acc[oi][1] * acc[oi][1]
                 + acc[oi][2] * acc[oi][2] + acc[oi][3] * acc[oi][3];
#pragma unroll
        for (int off = 8; off; off >>= 1) {
            s  += __shfl_down_sync(0xffffffffu, s,  off, 16);
            sq += __shfl_down_sync(0xffffffffu, sq, off, 16);
        }
        if (pw == 0) { atomicAdd(&g_sum1[o], s); atomicAdd(&g_sq1[o], sq); }
    }
}

// -------- K3/K5: fold BN stats --------
__global__ void k_bn1(const float* __restrict__ gamma, const float* __restrict__ beta) {
    int c = threadIdx.x;
    float m  = g_sum1[c] * (1.f / 16384.f);
    float vv = g_sq1[c]  * (1.f / 16384.f) - m * m;
    float sc = gamma[c] * rsqrtf(vv + 1e-5f);
    g_scale1[c] = sc;
    g_shift1[c] = beta[c] - m * sc;
}
__global__ void k_bn2(const float* __restrict__ gamma, const float* __restrict__ beta) {
    int c = threadIdx.x;
    float m  = g_sum2[c] * (1.f / 16384.f);
    float vv = g_sq2[c]  * (1.f / 16384.f) - m * m;
    float sc = gamma[c] * rsqrtf(vv + 1e-5f);
    g_scale2[c] = sc;
    g_shift2[c] = beta[c] - m * sc;
}

// -------- K4: conv3x3 (128->128), BN1+ReLU at load; writes raw + BN2 stats --------
__global__ __launch_bounds__(256) void k_conv2() {
    int b = blockIdx.x >> 6; int h = blockIdx.x & 63;
    int tid = threadIdx.x; int w = tid & 63; int q = tid >> 6;

    __shared__ float sx[8 * 3 * 64];     // 6 KB
    __shared__ float sw[8 * 9 * 128];    // 36 KB  [ci][kk][co]

    unsigned long long accp[16];         // co pairs: q*32 + 2p, 2p+1
#pragma unroll
    for (int p = 0; p < 16; p++) accp[p] = 0ull;

    for (int ch = 0; ch < 16; ch++) {
        int ci0 = ch * 8;
        __syncthreads();
        for (int i = tid; i < 8 * 9 * 128; i += 256) sw[i] = g_wT2[ci0 * 1152 + i];
        for (int i = tid; i < 8 * 3 * 64; i += 256) {
            int ci = i / 192; int r = (i >> 6) % 3; int wc = i & 63;
            int hh = h - 1 + r; int c = ci0 + ci;
            float v = 0.f;
            if (hh >= 0 && hh < 64) {
                float raw = g_out1[((size_t)(b * 128 + c) * 64 + hh) * 64 + wc];
                v = fmaxf(0.f, raw * g_scale1[c] + g_shift1[c]);
            }
            sx[i] = v;
        }
        __syncthreads();

        for (int ci = 0; ci < 8; ci++) {
#pragma unroll
            for (int kk = 0; kk < 9; kk++) {
                int ky = kk / 3, kx = kk % 3;
                int ww = w + kx - 1;
                float xval = (ww >= 0 && ww < 64) ? sx[ci * 192 + ky * 64 + ww] : 0.f;
                unsigned long long xb = pack2b(xval);
                const ulonglong2* wrow = (const ulonglong2*)&sw[(ci * 9 + kk) * 128 + q * 32];
#pragma unroll
                for (int j4 = 0; j4 < 8; j4++) {
                    ulonglong2 wv = wrow[j4];
                    FFMA2(accp[2 * j4],     wv.x, xb);
                    FFMA2(accp[2 * j4 + 1], wv.y, xb);
                }
            }
        }
    }

#pragma unroll
    for (int p = 0; p < 16; p++) {
        float2 f2 = unpack2(accp[p]);
#pragma unroll
        for (int s2 = 0; s2 < 2; s2++) {
            int co = q * 32 + 2 * p + s2;
            float v = (s2 == 0) ? f2.x : f2.y;
            g_out2[((size_t)(b * 128 + co) * 64 + h) * 64 + w] = v;
            float s = v, sq = v * v;
#pragma unroll
            for (int off = 16; off; off >>= 1) {
                s  += __shfl_down_sync(0xffffffffu, s,  off);
                sq += __shfl_down_sync(0xffffffffu, sq, off);
            }
            if ((tid & 31) == 0) { atomicAdd(&g_sum2[co], s); atomicAdd(&g_sq2[co], sq); }
        }
    }
}

// -------- K6: final BN2 + ReLU elementwise into d_out (vectorized) --------
__global__ void k_final(float* __restrict__ out) {
    int idx = blockIdx.x * 256 + threadIdx.x;   // 524288 float4's
    const float4* in4 = (const float4*)g_out2;
    float4 v = in4[idx];
    int c = (idx >> 10) & 127;
    float sc = g_scale2[c], sh = g_shift2[c];
    float4 r;
    r.x = fmaxf(0.f, v.x * sc + sh);
    r.y = fmaxf(0.f, v.y * sc + sh);
    r.z = fmaxf(0.f, v.z * sc + sh);
    r.w = fmaxf(0.f, v.w * sc + sh);
    ((float4*)out)[idx] = r;
}

// -------- host launcher (graph-capturable) --------
extern "C" void kernel_launch(void* const* d_in, const int* in_sizes, int n_in,
                              void* d_out, int out_size) {
    const float* input_v = (const float*)d_in[0];
    const float* input_i = (const float*)d_in[1];
    const float* off_w   = (const float*)d_in[2];
    const float* off_b   = (const float*)d_in[3];
    const float* dconv_w = (const float*)d_in[4];
    const float* bn1_g   = (const float*)d_in[5];
    const float* bn1_b   = (const float*)d_in[6];
    const float* conv2_w = (const float*)d_in[7];
    const float* bn2_g   = (const float*)d_in[8];
    const float* bn2_b   = (const float*)d_in[9];
    float* out = (float*)d_out;

    k_transpose<<<2214, 256>>>(dconv_w, off_w, conv2_w);
    k_offconv<<<NB * NH, 256>>>(input_v, input_i, off_b);
    k_deform<<<NB * NH, 256>>>(input_v, input_i);
    k_bn1<<<1, 128>>>(bn1_g, bn1_b);
    k_conv2<<<NB * NH, 256>>>();
    k_bn2<<<1, 128>>>(bn2_g, bn2_b);
    k_final<<<2048, 256>>>(out);
}

// round 4
// speedup vs baseline: 1.2694x; 1.0718x over previous
#include <cuda_runtime.h>
#include <math.h>

#define NB   4
#define CM   128
#define CTOT 256
#define NO   128
#define NH   64
#define NW   64
#define NHW  4096
#define OFFC 54

// ---- packed f32x2 helpers (Blackwell PTX-only FFMA2 path) ----
#define FFMA2(d, a, b) asm("fma.rn.f32x2 %0, %1, %2, %0;" : "+l"(d) : "l"(a), "l"(b))
__device__ __forceinline__ unsigned long long pack2b(float x) {
    unsigned long long r; asm("mov.b64 %0, {%1, %1};" : "=l"(r) : "f"(x)); return r;
}
__device__ __forceinline__ float2 unpack2(unsigned long long v) {
    float2 f; asm("mov.b64 {%0, %1}, %2;" : "=f"(f.x), "=f"(f.y) : "l"(v)); return f;
}

// -------- device scratch --------
__device__ float g_off  [NB*OFFC*NHW];
__device__ float g_offa [NB*OFFC*NHW];
__device__ float g_offb [NB*OFFC*NHW];
__device__ float g_wT  [2*9*128*128];        // dconv_w: [g][k][c][o]
__device__ float g_wT1 [CTOT*9*OFFC];        // off_w:   [ci][kk][co]
__device__ float g_wT2 [NO*9*NO];            // conv2_w: [ci][kk][co]
__device__ float g_out1 [NB*NO*NHW];
__device__ float g_out1a[NB*NO*NHW];
__device__ float g_out1b[NB*NO*NHW];
__device__ float g_out2 [NB*NO*NHW];
__device__ float g_out2a[NB*NO*NHW];
__device__ float g_out2b[NB*NO*NHW];
__device__ float g_scale1[NO], g_shift1[NO], g_scale2[NO], g_shift2[NO];

// -------- K0: transpose all weights --------
__global__ void k_transpose(const float* __restrict__ dconv_w,
                            const float* __restrict__ off_w,
                            const float* __restrict__ conv2_w) {
    int idx = blockIdx.x * 256 + threadIdx.x;
    if (idx < 294912) {
        int o = idx & 127; int c = (idx >> 7) & 127; int gk = idx >> 14;
        int k = gk % 9; int g = gk / 9;
        g_wT[idx] = dconv_w[(o * 256 + g * 128 + c) * 9 + k];
    } else if (idx < 294912 + 124416) {
        int j = idx - 294912;
        int co = j % 54; int a = j / 54; int ci = a / 9; int kk = a % 9;
        g_wT1[j] = off_w[(co * 256 + ci) * 9 + kk];
    } else if (idx < 294912 + 124416 + 147456) {
        int j = idx - 419328;
        int co = j & 127; int a = j >> 7; int ci = a / 9; int kk = a % 9;
        g_wT2[j] = conv2_w[(co * 128 + ci) * 9 + kk];
    }
}

// -------- K1: offset conv3x3, split by modality half. grid 512 --------
__global__ __launch_bounds__(256) void k_offconv(const float* __restrict__ xv,
                                                 const float* __restrict__ xi) {
    int half = blockIdx.x >> 8; int rem = blockIdx.x & 255;
    int b = rem >> 6; int h = rem & 63;
    int tid = threadIdx.x; int w = tid & 63; int q = tid >> 6;
    const float* xsrc = half ? xi : xv;
    float* outbuf = half ? g_offb : g_offa;

    __shared__ float sx[16 * 3 * 64];          // [ci][r][w]
    __shared__ float sw[16 * 9 * 4 * 16];      // [a][q][j(16)]

    unsigned long long accp[8];
#pragma unroll
    for (int p = 0; p < 8; p++) accp[p] = 0ull;

    for (int ch = 0; ch < 8; ch++) {
        int ci0 = half * 128 + ch * 16;        // global ci base (weights)
        int cl0 = ch * 16;                     // local base within modality
        __syncthreads();
        for (int i = tid; i < 16 * 9 * 4 * 2; i += 256) {
            int j = 14 + (i & 1); int aq = i >> 1;
            sw[aq * 16 + j] = 0.f;
        }
        for (int i = tid; i < 16 * 9 * 54; i += 256) {
            int a = i / 54; int co = i - a * 54;
            sw[(a * 4 + (co & 3)) * 16 + (co >> 2)] = g_wT1[ci0 * (9 * 54) + i];
        }
        for (int i = tid; i < 16 * 3 * 64; i += 256) {
            int ci = i / 192; int r = (i >> 6) % 3; int wc = i & 63;
            int hh = h - 1 + r;
            float v = 0.f;
            if (hh >= 0 && hh < 64)
                v = xsrc[((size_t)(b * 128 + cl0 + ci) * 64 + hh) * 64 + wc];
            sx[i] = v;
        }
        __syncthreads();

        for (int ci = 0; ci < 16; ci++) {
#pragma unroll
            for (int kk = 0; kk < 9; kk++) {
                int kx = kk % 3;
                int ky = kk / 3;
                int ww = w + kx - 1;
                float xval = (ww >= 0 && ww < 64) ? sx[ci * 192 + ky * 64 + ww] : 0.f;
                unsigned long long xb = pack2b(xval);
                const ulonglong2* wrow = (const ulonglong2*)&sw[((ci * 9 + kk) * 4 + q) * 16];
#pragma unroll
                for (int j4 = 0; j4 < 4; j4++) {
                    ulonglong2 wv = wrow[j4];
                    FFMA2(accp[2 * j4],     wv.x, xb);
                    FFMA2(accp[2 * j4 + 1], wv.y, xb);
                }
            }
        }
    }

#pragma unroll
    for (int p = 0; p < 8; p++) {
        float2 f2 = unpack2(accp[p]);
        int j0 = (p >> 1) * 4 + (p & 1) * 2;
#pragma unroll
        for (int s = 0; s < 2; s++) {
            int co = q + 4 * (j0 + s);
            if (co < 54)
                outbuf[((size_t)(b * 54 + co) * 64 + h) * 64 + w] = (s == 0 ? f2.x : f2.y);
        }
    }
}

// -------- K1b: combine halves + bias + sigmoid --------
__global__ void k_offpost(const float* __restrict__ off_b) {
    int idx = blockIdx.x * 256 + threadIdx.x;     // 884736 total
    int co = (idx >> 12) % 54;
    float v = g_offa[idx] + g_offb[idx] + off_b[co];
    if (co >= 36) v = 1.f / (1.f + expf(-v));
    g_off[idx] = v;
}

// -------- K2: deform-sample + grouped GEMM, split by group g. grid 512 --------
__global__ __launch_bounds__(256) void k_deform(const float* __restrict__ xv,
                                                const float* __restrict__ xi) {
    int g = blockIdx.x >> 8; int rem = blockIdx.x & 255;
    int b = rem >> 6; int h = rem & 63;
    int tid = threadIdx.x;
    int og = tid >> 4; int pw = tid & 15;
    float* outbuf = g ? g_out1b : g_out1a;
    const float* xbase = (g == 0 ? xv : xi) + (size_t)b * 128 * NHW;

    __shared__ float sv [32 * 64];
    __shared__ float swt[32 * 128];
    __shared__ int   si[4][64];
    __shared__ float sb[4][64];

    unsigned long long accp[4][4];
#pragma unroll
    for (int op = 0; op < 4; op++)
#pragma unroll
        for (int pi = 0; pi < 4; pi++) accp[op][pi] = 0ull;

    for (int k = 0; k < 9; k++) {
        int ky = k / 3 - 1, kx = (k % 3) - 1;
        __syncthreads();
        if (tid < 64) {
            int w = tid;
            const float* offp = g_off + (size_t)b * 54 * NHW + h * 64 + w;
            float dy = offp[(size_t)(g * 18 + 2 * k) * NHW];
            float dx = offp[(size_t)(g * 18 + 2 * k + 1) * NHW];
            float m  = offp[(size_t)(36 + g * 9 + k) * NHW];
            float py = dy + (float)(h + ky);
            float px = dx + (float)(w + kx);
            float fy = floorf(py), fx = floorf(px);
            float ly = py - fy,   lx = px - fx;
            int y0 = (int)fy, x0 = (int)fx;
            int y1 = y0 + 1,  x1 = x0 + 1;
            float o00 = (y0 >= 0 && y0 < 64 && x0 >= 0 && x0 < 64) ? 1.f : 0.f;
            float o01 = (y0 >= 0 && y0 < 64 && x1 >= 0 && x1 < 64) ? 1.f : 0.f;
            float o10 = (y1 >= 0 && y1 < 64 && x0 >= 0 && x0 < 64) ? 1.f : 0.f;
            float o11 = (y1 >= 0 && y1 < 64 && x1 >= 0 && x1 < 64) ? 1.f : 0.f;
            int cy0 = min(max(y0, 0), 63), cx0 = min(max(x0, 0), 63);
            int cy1 = min(max(y1, 0), 63), cx1 = min(max(x1, 0), 63);
            si[0][w] = cy0 * 64 + cx0;  si[1][w] = cy0 * 64 + cx1;
            si[2][w] = cy1 * 64 + cx0;  si[3][w] = cy1 * 64 + cx1;
            sb[0][w] = (1.f - ly) * (1.f - lx) * o00 * m;
            sb[1][w] = (1.f - ly) * lx         * o01 * m;
            sb[2][w] = ly * (1.f - lx)         * o10 * m;
            sb[3][w] = ly * lx                 * o11 * m;
        }
        __syncthreads();

        for (int cc = 0; cc < 4; cc++) {
            const float* wp = g_wT + ((size_t)(g * 9 + k) * 128 + cc * 32) * 128;
#pragma unroll
            for (int i = 0; i < 16; i++) swt[tid + i * 256] = wp[tid + i * 256];
#pragma unroll
            for (int i = 0; i < 8; i++) {
                int lin = tid + i * 256;
                int c = lin >> 6, pos = lin & 63;
                const float* xp = xbase + (size_t)(cc * 32 + c) * NHW;
                sv[lin] = sb[0][pos] * __ldg(xp + si[0][pos])
                        + sb[1][pos] * __ldg(xp + si[1][pos])
                        + sb[2][pos] * __ldg(xp + si[2][pos])
                        + sb[3][pos] * __ldg(xp + si[3][pos]);
            }
            __syncthreads();
#pragma unroll
            for (int c = 0; c < 32; c++) {
                float4 xa = *(const float4*)&sv[c * 64 + pw * 4];
                unsigned long long xp0 = pack2b(xa.x), xp1 = pack2b(xa.y);
                unsigned long long xp2 = pack2b(xa.z), xp3 = pack2b(xa.w);
                ulonglong2 wv0 = *(const ulonglong2*)&swt[c * 128 + og * 8];
                ulonglong2 wv1 = *(const ulonglong2*)&swt[c * 128 + og * 8 + 4];
                FFMA2(accp[0][0], wv0.x, xp0); FFMA2(accp[0][1], wv0.x, xp1);
                FFMA2(accp[0][2], wv0.x, xp2); FFMA2(accp[0][3], wv0.x, xp3);
                FFMA2(accp[1][0], wv0.y, xp0); FFMA2(accp[1][1], wv0.y, xp1);
                FFMA2(accp[1][2], wv0.y, xp2); FFMA2(accp[1][3], wv0.y, xp3);
                FFMA2(accp[2][0], wv1.x, xp0); FFMA2(accp[2][1], wv1.x, xp1);
                FFMA2(accp[2][2], wv1.x, xp2); FFMA2(accp[2][3], wv1.x, xp3);
                FFMA2(accp[3][0], wv1.y, xp0); FFMA2(accp[3][1], wv1.y, xp1);
                FFMA2(accp[3][2], wv1.y, xp2); FFMA2(accp[3][3], wv1.y, xp3);
            }
            __syncthreads();
        }
    }

    float* outp = outbuf + ((size_t)(b * 128) * 64 + h) * 64;
#pragma unroll
    for (int op = 0; op < 4; op++)
#pragma unroll
        for (int pi = 0; pi < 4; pi++) {
            float2 f2 = unpack2(accp[op][pi]);
            int o0 = og * 8 + 2 * op;
            outp[(size_t)o0 * NHW + pw * 4 + pi]       = f2.x;
            outp[(size_t)(o0 + 1) * NHW + pw * 4 + pi] = f2.y;
        }
}

// -------- K3: combine deform halves + BN1 stats + fold scale/shift --------
__global__ __launch_bounds__(256) void k_bn1(const float* __restrict__ gamma,
                                             const float* __restrict__ beta) {
    int c = blockIdx.x; int tid = threadIdx.x;
    __shared__ float ssum[256], ssq[256];
    float s = 0.f, sq = 0.f;
    for (int b = 0; b < NB; b++) {
        const float4* pa = (const float4*)(g_out1a + (size_t)(b * 128 + c) * NHW);
        const float4* pb = (const float4*)(g_out1b + (size_t)(b * 128 + c) * NHW);
        float4* po = (float4*)(g_out1 + (size_t)(b * 128 + c) * NHW);
        for (int i = tid; i < 1024; i += 256) {
            float4 va = pa[i], vb = pb[i];
            float4 v = make_float4(va.x + vb.x, va.y + vb.y, va.z + vb.z, va.w + vb.w);
            po[i] = v;
            s  += v.x + v.y + v.z + v.w;
            sq += v.x * v.x + v.y * v.y + v.z * v.z + v.w * v.w;
        }
    }
    ssum[tid] = s; ssq[tid] = sq;
    __syncthreads();
    for (int st = 128; st; st >>= 1) {
        if (tid < st) { ssum[tid] += ssum[tid + st]; ssq[tid] += ssq[tid + st]; }
        __syncthreads();
    }
    if (tid == 0) {
        float m  = ssum[0] * (1.f / 16384.f);
        float vv = ssq[0]  * (1.f / 16384.f) - m * m;
        float sc = gamma[c] * rsqrtf(vv + 1e-5f);
        g_scale1[c] = sc;
        g_shift1[c] = beta[c] - m * sc;
    }
}

// -------- K4: conv3x3 (128->128), BN1+ReLU at load, split by ci half. grid 512 --------
__global__ __launch_bounds__(256) void k_conv2() {
    int half = blockIdx.x >> 8; int rem = blockIdx.x & 255;
    int b = rem >> 6; int h = rem & 63;
    int tid = threadIdx.x; int w = tid & 63; int q = tid >> 6;
    float* outbuf = half ? g_out2b : g_out2a;

    __shared__ float sx[8 * 3 * 64];
    __shared__ float sw[8 * 9 * 128];

    unsigned long long accp[16];
#pragma unroll
    for (int p = 0; p < 16; p++) accp[p] = 0ull;

    for (int ch = 0; ch < 8; ch++) {
        int ci0 = half * 64 + ch * 8;
        __syncthreads();
        for (int i = tid; i < 8 * 9 * 128; i += 256) sw[i] = g_wT2[ci0 * 1152 + i];
        for (int i = tid; i < 8 * 3 * 64; i += 256) {
            int ci = i / 192; int r = (i >> 6) % 3; int wc = i & 63;
            int hh = h - 1 + r; int c = ci0 + ci;
            float v = 0.f;
            if (hh >= 0 && hh < 64) {
                float raw = g_out1[((size_t)(b * 128 + c) * 64 + hh) * 64 + wc];
                v = fmaxf(0.f, raw * g_scale1[c] + g_shift1[c]);
            }
            sx[i] = v;
        }
        __syncthreads();

        for (int ci = 0; ci < 8; ci++) {
#pragma unroll
            for (int kk = 0; kk < 9; kk++) {
                int ky = kk / 3, kx = kk % 3;
                int ww = w + kx - 1;
                float xval = (ww >= 0 && ww < 64) ? sx[ci * 192 + ky * 64 + ww] : 0.f;
                unsigned long long xb = pack2b(xval);
                const ulonglong2* wrow = (const ulonglong2*)&sw[(ci * 9 + kk) * 128 + q * 32];
#pragma unroll
                for (int j4 = 0; j4 < 8; j4++) {
                    ulonglong2 wv = wrow[j4];
                    FFMA2(accp[2 * j4],     wv.x, xb);
                    FFMA2(accp[2 * j4 + 1], wv.y, xb);
                }
            }
        }
    }

#pragma unroll
    for (int p = 0; p < 16; p++) {
        float2 f2 = unpack2(accp[p]);
        int co = q * 32 + 2 * p;
        outbuf[((size_t)(b * 128 + co) * 64 + h) * 64 + w]     = f2.x;
        outbuf[((size_t)(b * 128 + co + 1) * 64 + h) * 64 + w] = f2.y;
    }
}

// -------- K5: combine conv2 halves + BN2 stats + fold --------
__global__ __launch_bounds__(256) void k_bn2(const float* __restrict__ gamma,
                                             const float* __restrict__ beta) {
    int c = blockIdx.x; int tid = threadIdx.x;
    __shared__ float ssum[256], ssq[256];
    float s = 0.f, sq = 0.f;
    for (int b = 0; b < NB; b++) {
        const float4* pa = (const float4*)(g_out2a + (size_t)(b * 128 + c) * NHW);
        const float4* pb = (const float4*)(g_out2b + (size_t)(b * 128 + c) * NHW);
        float4* po = (float4*)(g_out2 + (size_t)(b * 128 + c) * NHW);
        for (int i = tid; i < 1024; i += 256) {
            float4 va = pa[i], vb = pb[i];
            float4 v = make_float4(va.x + vb.x, va.y + vb.y, va.z + vb.z, va.w + vb.w);
            po[i] = v;
            s  += v.x + v.y + v.z + v.w;
            sq += v.x * v.x + v.y * v.y + v.z * v.z + v.w * v.w;
        }
    }
    ssum[tid] = s; ssq[tid] = sq;
    __syncthreads();
    for (int st = 128; st; st >>= 1) {
        if (tid < st) { ssum[tid] += ssum[tid + st]; ssq[tid] += ssq[tid + st]; }
        __syncthreads();
    }
    if (tid == 0) {
        float m  = ssum[0] * (1.f / 16384.f);
        float vv = ssq[0]  * (1.f / 16384.f) - m * m;
        float sc = gamma[c] * rsqrtf(vv + 1e-5f);
        g_scale2[c] = sc;
        g_shift2[c] = beta[c] - m * sc;
    }
}

// -------- K6: final BN2 + ReLU elementwise into d_out --------
__global__ void k_final(float* __restrict__ out) {
    int idx = blockIdx.x * 256 + threadIdx.x;   // 524288 float4's
    const float4* in4 = (const float4*)g_out2;
    float4 v = in4[idx];
    int c = (idx >> 10) & 127;
    float sc = g_scale2[c], sh = g_shift2[c];
    float4 r;
    r.x = fmaxf(0.f, v.x * sc + sh);
    r.y = fmaxf(0.f, v.y * sc + sh);
    r.z = fmaxf(0.f, v.z * sc + sh);
    r.w = fmaxf(0.f, v.w * sc + sh);
    ((float4*)out)[idx] = r;
}

// -------- host launcher (graph-capturable) --------
extern "C" void kernel_launch(void* const* d_in, const int* in_sizes, int n_in,
                              void* d_out, int out_size) {
    const float* input_v = (const float*)d_in[0];
    const float* input_i = (const float*)d_in[1];
    const float* off_w   = (const float*)d_in[2];
    const float* off_b   = (const float*)d_in[3];
    const float* dconv_w = (const float*)d_in[4];
    const float* bn1_g   = (const float*)d_in[5];
    const float* bn1_b   = (const float*)d_in[6];
    const float* conv2_w = (const float*)d_in[7];
    const float* bn2_g   = (const float*)d_in[8];
    const float* bn2_b   = (const float*)d_in[9];
    float* out = (float*)d_out;

    k_transpose<<<2214, 256>>>(dconv_w, off_w, conv2_w);
    k_offconv<<<512, 256>>>(input_v, input_i);
    k_offpost<<<3456, 256>>>(off_b);
    k_deform<<<512, 256>>>(input_v, input_i);
    k_bn1<<<128, 256>>>(bn1_g, bn1_b);
    k_conv2<<<512, 256>>>();
    k_bn2<<<128, 256>>>(bn2_g, bn2_b);
    k_final<<<2048, 256>>>(out);
}

// round 9
// speedup vs baseline: 1.3151x; 1.0360x over previous
#include <cuda_runtime.h>
#include <math.h>
#include <stdint.h>

#define NB   4
#define CM   128
#define CTOT 256
#define NO   128
#define NH   64
#define NW   64
#define NHW  4096
#define OFFC 54

// ---- packed f32x2 helpers (Blackwell FFMA2 path) ----
#define FFMA2(d, a, b) asm("fma.rn.f32x2 %0, %1, %2, %0;" : "+l"(d) : "l"(a), "l"(b))
__device__ __forceinline__ unsigned long long pack2b(float x) {
    unsigned long long r; asm("mov.b64 %0, {%1, %1};" : "=l"(r) : "f"(x)); return r;
}
__device__ __forceinline__ float2 unpack2(unsigned long long v) {
    float2 f; asm("mov.b64 {%0, %1}, %2;" : "=f"(f.x), "=f"(f.y) : "l"(v)); return f;
}

// -------- device scratch --------
__device__ float g_off  [NB*OFFC*NHW];
__device__ float g_offs [4*NB*OFFC*NHW];       // offconv quarter partials
__device__ float g_xT   [8*4096*128];          // NHWC input: [b*2+g][pos][c]
__device__ float g_wT   [2*9*128*128];         // dconv_w: [g][k][c][o]
__device__ float g_wT1  [CTOT*9*OFFC];         // off_w:   [ci][kk][co]
__device__ float g_wT2  [NO*9*NO];             // conv2_w: [ci][kk][co]
__device__ float g_out1 [NB*NO*NHW];
__device__ float g_out1s[4*NB*NO*NHW];         // deform partials (g x chalf)
__device__ float g_out2 [NB*NO*NHW];
__device__ float g_out2s[4*NB*NO*NHW];         // conv2 quarter partials
__device__ float g_scale1[NO], g_shift1[NO], g_scale2[NO], g_shift2[NO];

// -------- K0: transpose all weights --------
__global__ void k_transpose(const float* __restrict__ dconv_w,
                            const float* __restrict__ off_w,
                            const float* __restrict__ conv2_w) {
    int idx = blockIdx.x * 256 + threadIdx.x;
    if (idx < 294912) {
        int o = idx & 127; int c = (idx >> 7) & 127; int gk = idx >> 14;
        int k = gk % 9; int g = gk / 9;
        g_wT[idx] = dconv_w[(o * 256 + g * 128 + c) * 9 + k];
    } else if (idx < 294912 + 124416) {
        int j = idx - 294912;
        int co = j % 54; int a = j / 54; int ci = a / 9; int kk = a % 9;
        g_wT1[j] = off_w[(co * 256 + ci) * 9 + kk];
    } else if (idx < 294912 + 124416 + 147456) {
        int j = idx - 419328;
        int co = j & 127; int a = j >> 7; int ci = a / 9; int kk = a % 9;
        g_wT2[j] = conv2_w[(co * 128 + ci) * 9 + kk];
    }
}

// -------- K0b: NCHW -> NHWC transpose of inputs (for vectorized gathers) --------
// grid 1024: bg = bx>>7 (8), pos-tile of 32 = bx&127. smem-tiled, conflict-free.
__global__ __launch_bounds__(256) void k_nhwc(const float* __restrict__ xv,
                                              const float* __restrict__ xi) {
    int bg = blockIdx.x >> 7; int tile = blockIdx.x & 127;
    int g = bg & 1; int b = bg >> 1;
    int pos0 = tile * 32;
    int tid = threadIdx.x;
    const float* src = (g ? xi : xv) + (size_t)b * 128 * NHW;
    __shared__ float s[128][33];
#pragma unroll
    for (int it = 0; it < 16; it++) {
        int i = tid + it * 256;
        int c = i >> 5; int p = i & 31;
        s[c][p] = src[(size_t)c * NHW + pos0 + p];
    }
    __syncthreads();
    float* dst = g_xT + ((size_t)bg * 4096 + pos0) * 128;
#pragma unroll
    for (int it = 0; it < 16; it++) {
        int j = tid + it * 256;
        int p = j >> 7; int c = j & 127;
        dst[(size_t)p * 128 + c] = s[c][p];
    }
}

// -------- K1: offset conv3x3, quarter ci split. grid 1024 --------
__global__ __launch_bounds__(256) void k_offconv(const float* __restrict__ xv,
                                                 const float* __restrict__ xi) {
    int quarter = blockIdx.x >> 8; int rem = blockIdx.x & 255;
    int b = rem >> 6; int h = rem & 63;
    int tid = threadIdx.x; int w = tid & 63; int q = tid >> 6;
    const float* xsrc = (quarter < 2) ? xv : xi;
    float* outbuf = g_offs + (size_t)quarter * (NB * OFFC * NHW);

    __shared__ float sx[16 * 3 * 64];
    __shared__ float sw[16 * 9 * 4 * 16];

    unsigned long long accp[8];
#pragma unroll
    for (int p = 0; p < 8; p++) accp[p] = 0ull;

    for (int ch = 0; ch < 4; ch++) {
        int ci0 = quarter * 64 + ch * 16;           // global ci (weights)
        int cl0 = (quarter & 1) * 64 + ch * 16;     // within-modality ci
        __syncthreads();
        for (int i = tid; i < 16 * 9 * 4 * 2; i += 256) {
            int j = 14 + (i & 1); int aq = i >> 1;
            sw[aq * 16 + j] = 0.f;
        }
        for (int i = tid; i < 16 * 9 * 54; i += 256) {
            int a = i / 54; int co = i - a * 54;
            sw[(a * 4 + (co & 3)) * 16 + (co >> 2)] = g_wT1[ci0 * (9 * 54) + i];
        }
        for (int i = tid; i < 16 * 3 * 64; i += 256) {
            int ci = i / 192; int r = (i >> 6) % 3; int wc = i & 63;
            int hh = h - 1 + r;
            float v = 0.f;
            if (hh >= 0 && hh < 64)
                v = xsrc[((size_t)(b * 128 + cl0 + ci) * 64 + hh) * 64 + wc];
            sx[i] = v;
        }
        __syncthreads();

        for (int ci = 0; ci < 16; ci++) {
#pragma unroll
            for (int kk = 0; kk < 9; kk++) {
                int kx = kk % 3, ky = kk / 3;
                int ww = w + kx - 1;
                float xval = (ww >= 0 && ww < 64) ? sx[ci * 192 + ky * 64 + ww] : 0.f;
                unsigned long long xb = pack2b(xval);
                const ulonglong2* wrow = (const ulonglong2*)&sw[((ci * 9 + kk) * 4 + q) * 16];
#pragma unroll
                for (int j4 = 0; j4 < 4; j4++) {
                    ulonglong2 wv = wrow[j4];
                    FFMA2(accp[2 * j4],     wv.x, xb);
                    FFMA2(accp[2 * j4 + 1], wv.y, xb);
                }
            }
        }
    }

#pragma unroll
    for (int p = 0; p < 8; p++) {
        float2 f2 = unpack2(accp[p]);
        int j0 = (p >> 1) * 4 + (p & 1) * 2;
#pragma unroll
        for (int s = 0; s < 2; s++) {
            int co = q + 4 * (j0 + s);
            if (co < 54)
                outbuf[((size_t)(b * 54 + co) * 64 + h) * 64 + w] = (s == 0 ? f2.x : f2.y);
        }
    }
}

// -------- K1b: combine 4 quarters + bias + sigmoid --------
__global__ void k_offpost(const float* __restrict__ off_b) {
    const int N = NB * OFFC * NHW;
    int idx = blockIdx.x * 256 + threadIdx.x;
    int co = (idx >> 12) % 54;
    float v = g_offs[idx] + g_offs[N + idx] + g_offs[2 * N + idx] + g_offs[3 * N + idx]
            + off_b[co];
    if (co >= 36) v = 1.f / (1.f + expf(-v));
    g_off[idx] = v;
}

// -------- K2: deform-sample + grouped GEMM, split by (g, c-half). grid 1024 --------
// CTA: (chalf, g, b, h). 64 c per CTA in 2 chunks of 32, double-buffered.
__global__ __launch_bounds__(256) void k_deform() {
    int bx = blockIdx.x;
    int ch2 = bx >> 9;              // c-half
    int g   = (bx >> 8) & 1;
    int b   = (bx >> 6) & 3;
    int h   = bx & 63;
    int tid = threadIdx.x;
    int og = tid >> 4; int pw = tid & 15;
    float* outbuf = g_out1s + (size_t)(g * 2 + ch2) * (NB * NO * NHW);
    const float4* xT4 = (const float4*)g_xT + (size_t)(b * 2 + g) * 4096 * 32;

    __shared__ float sv [2][2048];     // [buf][32 c][64 px]
    __shared__ float swt[2][4096];     // [buf][32 c][128 o]
    __shared__ int   si[4][64];
    __shared__ float sb[4][64];

    unsigned long long accp[4][4];
#pragma unroll
    for (int op = 0; op < 4; op++)
#pragma unroll
        for (int pi = 0; pi < 4; pi++) accp[op][pi] = 0ull;

    int cnt = 0;
    for (int k = 0; k < 9; k++) {
        int ky = k / 3 - 1, kx = (k % 3) - 1;
        __syncthreads();               // prior gathers done reading si/sb
        if (tid < 64) {
            int w = tid;
            const float* offp = g_off + (size_t)b * 54 * NHW + h * 64 + w;
            float dy = offp[(size_t)(g * 18 + 2 * k) * NHW];
            float dx = offp[(size_t)(g * 18 + 2 * k + 1) * NHW];
            float m  = offp[(size_t)(36 + g * 9 + k) * NHW];
            float py = dy + (float)(h + ky);
            float px = dx + (float)(w + kx);
            float fy = floorf(py), fx = floorf(px);
            float ly = py - fy,   lx = px - fx;
            int y0 = (int)fy, x0 = (int)fx;
            int y1 = y0 + 1,  x1 = x0 + 1;
            float o00 = (y0 >= 0 && y0 < 64 && x0 >= 0 && x0 < 64) ? 1.f : 0.f;
            float o01 = (y0 >= 0 && y0 < 64 && x1 >= 0 && x1 < 64) ? 1.f : 0.f;
            float o10 = (y1 >= 0 && y1 < 64 && x0 >= 0 && x0 < 64) ? 1.f : 0.f;
            float o11 = (y1 >= 0 && y1 < 64 && x1 >= 0 && x1 < 64) ? 1.f : 0.f;
            int cy0 = min(max(y0, 0), 63), cx0 = min(max(x0, 0), 63);
            int cy1 = min(max(y1, 0), 63), cx1 = min(max(x1, 0), 63);
            si[0][w] = cy0 * 64 + cx0;  si[1][w] = cy0 * 64 + cx1;
            si[2][w] = cy1 * 64 + cx0;  si[3][w] = cy1 * 64 + cx1;
            sb[0][w] = (1.f - ly) * (1.f - lx) * o00 * m;
            sb[1][w] = (1.f - ly) * lx         * o01 * m;
            sb[2][w] = ly * (1.f - lx)         * o10 * m;
            sb[3][w] = ly * lx                 * o11 * m;
        }
        __syncthreads();

        for (int cc = 0; cc < 2; cc++) {
            int buf = cnt & 1;
            int c0 = ch2 * 64 + cc * 32;
            // stage weights [32 c][128 o]
            const float* wp = g_wT + ((size_t)(g * 9 + k) * 128 + c0) * 128;
            float* swb = swt[buf];
#pragma unroll
            for (int i = 0; i < 16; i++) swb[tid + i * 256] = wp[tid + i * 256];
            // gather: NHWC float4 loads, 2 tasks per thread
            float* svb = sv[buf];
#pragma unroll
            for (int t = 0; t < 2; t++) {
                int lin = tid + t * 256;       // 512 tasks: (c4, px)
                int c4 = lin >> 6; int px = lin & 63;
                const float4* bp = xT4 + (c0 >> 2) + c4;
                float4 q0 = __ldg(bp + si[0][px] * 32);
                float4 q1 = __ldg(bp + si[1][px] * 32);
                float4 q2 = __ldg(bp + si[2][px] * 32);
                float4 q3 = __ldg(bp + si[3][px] * 32);
                float b0 = sb[0][px], b1 = sb[1][px], b2 = sb[2][px], b3 = sb[3][px];
                float* svp = svb + c4 * 256 + px;
                svp[0]   = b0 * q0.x + b1 * q1.x + b2 * q2.x + b3 * q3.x;
                svp[64]  = b0 * q0.y + b1 * q1.y + b2 * q2.y + b3 * q3.y;
                svp[128] = b0 * q0.z + b1 * q1.z + b2 * q2.z + b3 * q3.z;
                svp[192] = b0 * q0.w + b1 * q1.w + b2 * q2.w + b3 * q3.w;
            }
            __syncthreads();
            // 8o x 4px FFMA2 register tile over 32-channel chunk
#pragma unroll
            for (int c = 0; c < 32; c++) {
                float4 xa = *(const float4*)&svb[c * 64 + pw * 4];
                unsigned long long xp0 = pack2b(xa.x), xp1 = pack2b(xa.y);
                unsigned long long xp2 = pack2b(xa.z), xp3 = pack2b(xa.w);
                ulonglong2 wv0 = *(const ulonglong2*)&swb[c * 128 + og * 8];
                ulonglong2 wv1 = *(const ulonglong2*)&swb[c * 128 + og * 8 + 4];
                FFMA2(accp[0][0], wv0.x, xp0); FFMA2(accp[0][1], wv0.x, xp1);
                FFMA2(accp[0][2], wv0.x, xp2); FFMA2(accp[0][3], wv0.x, xp3);
                FFMA2(accp[1][0], wv0.y, xp0); FFMA2(accp[1][1], wv0.y, xp1);
                FFMA2(accp[1][2], wv0.y, xp2); FFMA2(accp[1][3], wv0.y, xp3);
                FFMA2(accp[2][0], wv1.x, xp0); FFMA2(accp[2][1], wv1.x, xp1);
                FFMA2(accp[2][2], wv1.x, xp2); FFMA2(accp[2][3], wv1.x, xp3);
                FFMA2(accp[3][0], wv1.y, xp0); FFMA2(accp[3][1], wv1.y, xp1);
                FFMA2(accp[3][2], wv1.y, xp2); FFMA2(accp[3][3], wv1.y, xp3);
            }
            cnt++;
        }
    }

    float* outp = outbuf + ((size_t)(b * 128) * 64 + h) * 64;
#pragma unroll
    for (int op = 0; op < 4; op++)
#pragma unroll
        for (int pi = 0; pi < 4; pi++) {
            float2 f2 = unpack2(accp[op][pi]);
            int o0 = og * 8 + 2 * op;
            outp[(size_t)o0 * NHW + pw * 4 + pi]       = f2.x;
            outp[(size_t)(o0 + 1) * NHW + pw * 4 + pi] = f2.y;
        }
}

// -------- K3: combine 4 deform partials + BN1 stats + fold --------
__global__ __launch_bounds__(256) void k_bn1(const float* __restrict__ gamma,
                                             const float* __restrict__ beta) {
    const size_t N = (size_t)NB * NO * NHW;
    int c = blockIdx.x; int tid = threadIdx.x;
    __shared__ float ssum[256], ssq[256];
    float s = 0.f, sq = 0.f;
    for (int b = 0; b < NB; b++) {
        size_t base = (size_t)(b * 128 + c) * NHW;
        const float4* p0 = (const float4*)(g_out1s + base);
        const float4* p1 = (const float4*)(g_out1s + N + base);
        const float4* p2 = (const float4*)(g_out1s + 2 * N + base);
        const float4* p3 = (const float4*)(g_out1s + 3 * N + base);
        float4* po = (float4*)(g_out1 + base);
        for (int i = tid; i < 1024; i += 256) {
            float4 a = p0[i], bq = p1[i], cq = p2[i], dq = p3[i];
            float4 v = make_float4(a.x + bq.x + cq.x + dq.x, a.y + bq.y + cq.y + dq.y,
                                   a.z + bq.z + cq.z + dq.z, a.w + bq.w + cq.w + dq.w);
            po[i] = v;
            s  += v.x + v.y + v.z + v.w;
            sq += v.x * v.x + v.y * v.y + v.z * v.z + v.w * v.w;
        }
    }
    ssum[tid] = s; ssq[tid] = sq;
    __syncthreads();
    for (int st = 128; st; st >>= 1) {
        if (tid < st) { ssum[tid] += ssum[tid + st]; ssq[tid] += ssq[tid + st]; }
        __syncthreads();
    }
    if (tid == 0) {
        float m  = ssum[0] * (1.f / 16384.f);
        float vv = ssq[0]  * (1.f / 16384.f) - m * m;
        float sc = gamma[c] * rsqrtf(vv + 1e-5f);
        g_scale1[c] = sc;
        g_shift1[c] = beta[c] - m * sc;
    }
}

// -------- K4: conv3x3 (128->128), BN1+ReLU at load, quarter ci split. grid 1024 --------
__global__ __launch_bounds__(256) void k_conv2() {
    int quarter = blockIdx.x >> 8; int rem = blockIdx.x & 255;
    int b = rem >> 6; int h = rem & 63;
    int tid = threadIdx.x; int w = tid & 63; int q = tid >> 6;
    float* outbuf = g_out2s + (size_t)quarter * (NB * NO * NHW);

    __shared__ float sx[8 * 3 * 64];
    __shared__ float sw[8 * 9 * 128];

    unsigned long long accp[16];
#pragma unroll
    for (int p = 0; p < 16; p++) accp[p] = 0ull;

    for (int ch = 0; ch < 4; ch++) {
        int ci0 = quarter * 32 + ch * 8;
        __syncthreads();
        for (int i = tid; i < 8 * 9 * 128; i += 256) sw[i] = g_wT2[ci0 * 1152 + i];
        for (int i = tid; i < 8 * 3 * 64; i += 256) {
            int ci = i / 192; int r = (i >> 6) % 3; int wc = i & 63;
            int hh = h - 1 + r; int c = ci0 + ci;
            float v = 0.f;
            if (hh >= 0 && hh < 64) {
                float raw = g_out1[((size_t)(b * 128 + c) * 64 + hh) * 64 + wc];
                v = fmaxf(0.f, raw * g_scale1[c] + g_shift1[c]);
            }
            sx[i] = v;
        }
        __syncthreads();

        for (int ci = 0; ci < 8; ci++) {
#pragma unroll
            for (int kk = 0; kk < 9; kk++) {
                int ky = kk / 3, kx = kk % 3;
                int ww = w + kx - 1;
                float xval = (ww >= 0 && ww < 64) ? sx[ci * 192 + ky * 64 + ww] : 0.f;
                unsigned long long xb = pack2b(xval);
                const ulonglong2* wrow = (const ulonglong2*)&sw[(ci * 9 + kk) * 128 + q * 32];
#pragma unroll
                for (int j4 = 0; j4 < 8; j4++) {
                    ulonglong2 wv = wrow[j4];
                    FFMA2(accp[2 * j4],     wv.x, xb);
                    FFMA2(accp[2 * j4 + 1], wv.y, xb);
                }
            }
        }
    }

#pragma unroll
    for (int p = 0; p < 16; p++) {
        float2 f2 = unpack2(accp[p]);
        int co = q * 32 + 2 * p;
        outbuf[((size_t)(b * 128 + co) * 64 + h) * 64 + w]     = f2.x;
        outbuf[((size_t)(b * 128 + co + 1) * 64 + h) * 64 + w] = f2.y;
    }
}

// -------- K5: combine 4 conv2 partials + BN2 stats + fold --------
__global__ __launch_bounds__(256) void k_bn2(const float* __restrict__ gamma,
                                             const float* __restrict__ beta) {
    const size_t N = (size_t)NB * NO * NHW;
    int c = blockIdx.x; int tid = threadIdx.x;
    __shared__ float ssum[256], ssq[256];
    float s = 0.f, sq = 0.f;
    for (int b = 0; b < NB; b++) {
        size_t base = (size_t)(b * 128 + c) * NHW;
        const float4* p0 = (const float4*)(g_out2s + base);
        const float4* p1 = (const float4*)(g_out2s + N + base);
        const float4* p2 = (const float4*)(g_out2s + 2 * N + base);
        const float4* p3 = (const float4*)(g_out2s + 3 * N + base);
        float4* po = (float4*)(g_out2 + base);
        for (int i = tid; i < 1024; i += 256) {
            float4 a = p0[i], bq = p1[i], cq = p2[i], dq = p3[i];
            float4 v = make_float4(a.x + bq.x + cq.x + dq.x, a.y + bq.y + cq.y + dq.y,
                                   a.z + bq.z + cq.z + dq.z, a.w + bq.w + cq.w + dq.w);
            po[i] = v;
            s  += v.x + v.y + v.z + v.w;
            sq += v.x * v.x + v.y * v.y + v.z * v.z + v.w * v.w;
        }
    }
    ssum[tid] = s; ssq[tid] = sq;
    __syncthreads();
    for (int st = 128; st; st >>= 1) {
        if (tid < st) { ssum[tid] += ssum[tid + st]; ssq[tid] += ssq[tid + st]; }
        __syncthreads();
    }
    if (tid == 0) {
        float m  = ssum[0] * (1.f / 16384.f);
        float vv = ssq[0]  * (1.f / 16384.f) - m * m;
        float sc = gamma[c] * rsqrtf(vv + 1e-5f);
        g_scale2[c] = sc;
        g_shift2[c] = beta[c] - m * sc;
    }
}

// -------- K6: final BN2 + ReLU elementwise into d_out --------
__global__ void k_final(float* __restrict__ out) {
    int idx = blockIdx.x * 256 + threadIdx.x;
    const float4* in4 = (const float4*)g_out2;
    float4 v = in4[idx];
    int c = (idx >> 10) & 127;
    float sc = g_scale2[c], sh = g_shift2[c];
    float4 r;
    r.x = fmaxf(0.f, v.x * sc + sh);
    r.y = fmaxf(0.f, v.y * sc + sh);
    r.z = fmaxf(0.f, v.z * sc + sh);
    r.w = fmaxf(0.f, v.w * sc + sh);
    ((float4*)out)[idx] = r;
}

// -------- host launcher (graph-capturable) --------
extern "C" void kernel_launch(void* const* d_in, const int* in_sizes, int n_in,
                              void* d_out, int out_size) {
    const float* input_v = (const float*)d_in[0];
    const float* input_i = (const float*)d_in[1];
    const float* off_w   = (const float*)d_in[2];
    const float* off_b   = (const float*)d_in[3];
    const float* dconv_w = (const float*)d_in[4];
    const float* bn1_g   = (const float*)d_in[5];
    const float* bn1_b   = (const float*)d_in[6];
    const float* conv2_w = (const float*)d_in[7];
    const float* bn2_g   = (const float*)d_in[8];
    const float* bn2_b   = (const float*)d_in[9];
    float* out = (float*)d_out;

    k_transpose<<<2214, 256>>>(dconv_w, off_w, conv2_w);
    k_nhwc<<<1024, 256>>>(input_v, input_i);
    k_offconv<<<1024, 256>>>(input_v, input_i);
    k_offpost<<<3456, 256>>>(off_b);
    k_deform<<<1024, 256>>>();
    k_bn1<<<128, 256>>>(bn1_g, bn1_b);
    k_conv2<<<1024, 256>>>();
    k_bn2<<<128, 256>>>(bn2_g, bn2_b);
    k_final<<<2048, 256>>>(out);
}

// round 10
// speedup vs baseline: 1.3683x; 1.0405x over previous
#include <cuda_runtime.h>
#include <math.h>
#include <stdint.h>

#define NB   4
#define CM   128
#define CTOT 256
#define NO   128
#define NH   64
#define NW   64
#define NHW  4096
#define OFFC 54

// ---- packed f32x2 helpers (Blackwell FFMA2 path) ----
#define FFMA2(d, a, b) asm("fma.rn.f32x2 %0, %1, %2, %0;" : "+l"(d) : "l"(a), "l"(b))
__device__ __forceinline__ unsigned long long pack2b(float x) {
    unsigned long long r; asm("mov.b64 %0, {%1, %1};" : "=l"(r) : "f"(x)); return r;
}
__device__ __forceinline__ float2 unpack2(unsigned long long v) {
    float2 f; asm("mov.b64 {%0, %1}, %2;" : "=f"(f.x), "=f"(f.y) : "l"(v)); return f;
}

// -------- device scratch --------
__device__ float g_off  [NB*OFFC*NHW];
__device__ float g_offs [4*NB*OFFC*NHW];       // offconv quarter partials
__device__ float g_xT   [8*4096*128];          // NHWC input: [b*2+g][pos][c]
__device__ float g_wT   [2*9*128*128];         // dconv_w: [g][k][c][o]
__device__ float g_wT1  [CTOT*9*OFFC];         // off_w:   [ci][kk][co]
__device__ float g_wT2  [NO*9*NO];             // conv2_w: [ci][kk][co]
__device__ float g_out1 [NB*NO*NHW];
__device__ float g_out1s[4*NB*NO*NHW];         // deform partials (g x chalf)
__device__ float g_out2 [NB*NO*NHW];
__device__ float g_out2s[4*NB*NO*NHW];         // conv2 quarter partials
__device__ float g_scale1[NO], g_shift1[NO], g_scale2[NO], g_shift2[NO];

// -------- K0: transpose all weights --------
__global__ void k_transpose(const float* __restrict__ dconv_w,
                            const float* __restrict__ off_w,
                            const float* __restrict__ conv2_w) {
    int idx = blockIdx.x * 256 + threadIdx.x;
    if (idx < 294912) {
        int o = idx & 127; int c = (idx >> 7) & 127; int gk = idx >> 14;
        int k = gk % 9; int g = gk / 9;
        g_wT[idx] = dconv_w[(o * 256 + g * 128 + c) * 9 + k];
    } else if (idx < 294912 + 124416) {
        int j = idx - 294912;
        int co = j % 54; int a = j / 54; int ci = a / 9; int kk = a % 9;
        g_wT1[j] = off_w[(co * 256 + ci) * 9 + kk];
    } else if (idx < 294912 + 124416 + 147456) {
        int j = idx - 419328;
        int co = j & 127; int a = j >> 7; int ci = a / 9; int kk = a % 9;
        g_wT2[j] = conv2_w[(co * 128 + ci) * 9 + kk];
    }
}

// -------- K0b: NCHW -> NHWC transpose of inputs --------
__global__ __launch_bounds__(256) void k_nhwc(const float* __restrict__ xv,
                                              const float* __restrict__ xi) {
    int bg = blockIdx.x >> 7; int tile = blockIdx.x & 127;
    int g = bg & 1; int b = bg >> 1;
    int pos0 = tile * 32;
    int tid = threadIdx.x;
    const float* src = (g ? xi : xv) + (size_t)b * 128 * NHW;
    __shared__ float s[128][33];
#pragma unroll
    for (int it = 0; it < 16; it++) {
        int i = tid + it * 256;
        int c = i >> 5; int p = i & 31;
        s[c][p] = src[(size_t)c * NHW + pos0 + p];
    }
    __syncthreads();
    float* dst = g_xT + ((size_t)bg * 4096 + pos0) * 128;
#pragma unroll
    for (int it = 0; it < 16; it++) {
        int j = tid + it * 256;
        int p = j >> 7; int c = j & 127;
        dst[(size_t)p * 128 + c] = s[c][p];
    }
}

// -------- K1: offset conv3x3, quarter ci split, halo tile. grid 1024 --------
__global__ __launch_bounds__(256) void k_offconv(const float* __restrict__ xv,
                                                 const float* __restrict__ xi) {
    int quarter = blockIdx.x >> 8; int rem = blockIdx.x & 255;
    int b = rem >> 6; int h = rem & 63;
    int tid = threadIdx.x; int w = tid & 63; int q = tid >> 6;
    const float* xsrc = (quarter < 2) ? xv : xi;
    float* outbuf = g_offs + (size_t)quarter * (NB * OFFC * NHW);

    __shared__ float sx[16 * 3 * 66];          // halo: wc = w+1, borders zero
    __shared__ float sw[16 * 9 * 4 * 16];

    unsigned long long accp[8];
#pragma unroll
    for (int p = 0; p < 8; p++) accp[p] = 0ull;

    for (int ch = 0; ch < 4; ch++) {
        int ci0 = quarter * 64 + ch * 16;           // global ci (weights)
        int cl0 = (quarter & 1) * 64 + ch * 16;     // within-modality ci
        __syncthreads();
        for (int i = tid; i < 16 * 9 * 4 * 2; i += 256) {
            int j = 14 + (i & 1); int aq = i >> 1;
            sw[aq * 16 + j] = 0.f;
        }
        for (int i = tid; i < 16 * 9 * 54; i += 256) {
            int a = i / 54; int co = i - a * 54;
            sw[(a * 4 + (co & 3)) * 16 + (co >> 2)] = g_wT1[ci0 * (9 * 54) + i];
        }
        for (int i = tid; i < 16 * 3 * 66; i += 256) {
            int ci = i / 198; int r2 = i - ci * 198; int r = r2 / 66; int wc = r2 - r * 66;
            int hh = h - 1 + r; int ww = wc - 1;
            float v = 0.f;
            if (hh >= 0 && hh < 64 && ww >= 0 && ww < 64)
                v = xsrc[((size_t)(b * 128 + cl0 + ci) * 64 + hh) * 64 + ww];
            sx[i] = v;
        }
        __syncthreads();

        for (int ci = 0; ci < 16; ci++) {
#pragma unroll
            for (int kk = 0; kk < 9; kk++) {
                int kx = kk % 3, ky = kk / 3;
                float xval = sx[ci * 198 + ky * 66 + w + kx];   // unconditional
                unsigned long long xb = pack2b(xval);
                const ulonglong2* wrow = (const ulonglong2*)&sw[((ci * 9 + kk) * 4 + q) * 16];
#pragma unroll
                for (int j4 = 0; j4 < 4; j4++) {
                    ulonglong2 wv = wrow[j4];
                    FFMA2(accp[2 * j4],     wv.x, xb);
                    FFMA2(accp[2 * j4 + 1], wv.y, xb);
                }
            }
        }
    }

#pragma unroll
    for (int p = 0; p < 8; p++) {
        float2 f2 = unpack2(accp[p]);
        int j0 = (p >> 1) * 4 + (p & 1) * 2;
#pragma unroll
        for (int s = 0; s < 2; s++) {
            int co = q + 4 * (j0 + s);
            if (co < 54)
                outbuf[((size_t)(b * 54 + co) * 64 + h) * 64 + w] = (s == 0 ? f2.x : f2.y);
        }
    }
}

// -------- K1b: combine 4 quarters + bias + sigmoid --------
__global__ void k_offpost(const float* __restrict__ off_b) {
    const int N = NB * OFFC * NHW;
    int idx = blockIdx.x * 256 + threadIdx.x;
    int co = (idx >> 12) % 54;
    float v = g_offs[idx] + g_offs[N + idx] + g_offs[2 * N + idx] + g_offs[3 * N + idx]
            + off_b[co];
    if (co >= 36) v = 1.f / (1.f + expf(-v));
    g_off[idx] = v;
}

// -------- K2: deform-sample + grouped GEMM, split by (g, c-half). grid 1024 --------
__global__ __launch_bounds__(256) void k_deform() {
    int bx = blockIdx.x;
    int ch2 = bx >> 9;              // c-half
    int g   = (bx >> 8) & 1;
    int b   = (bx >> 6) & 3;
    int h   = bx & 63;
    int tid = threadIdx.x;
    int og = tid >> 4; int pw = tid & 15;
    float* outbuf = g_out1s + (size_t)(g * 2 + ch2) * (NB * NO * NHW);
    const float4* xT4 = (const float4*)g_xT + (size_t)(b * 2 + g) * 4096 * 32;

    __shared__ float sv [2][2048];     // [buf][32 c][64 px]
    __shared__ float swt[2][4096];     // [buf][32 c][128 o]
    __shared__ int   si[4][64];
    __shared__ float sb[4][64];

    unsigned long long accp[4][4];
#pragma unroll
    for (int op = 0; op < 4; op++)
#pragma unroll
        for (int pi = 0; pi < 4; pi++) accp[op][pi] = 0ull;

    int cnt = 0;
    for (int k = 0; k < 9; k++) {
        int ky = k / 3 - 1, kx = (k % 3) - 1;
        __syncthreads();
        if (tid < 64) {
            int w = tid;
            const float* offp = g_off + (size_t)b * 54 * NHW + h * 64 + w;
            float dy = offp[(size_t)(g * 18 + 2 * k) * NHW];
            float dx = offp[(size_t)(g * 18 + 2 * k + 1) * NHW];
            float m  = offp[(size_t)(36 + g * 9 + k) * NHW];
            float py = dy + (float)(h + ky);
            float px = dx + (float)(w + kx);
            float fy = floorf(py), fx = floorf(px);
            float ly = py - fy,   lx = px - fx;
            int y0 = (int)fy, x0 = (int)fx;
            int y1 = y0 + 1,  x1 = x0 + 1;
            float o00 = (y0 >= 0 && y0 < 64 && x0 >= 0 && x0 < 64) ? 1.f : 0.f;
            float o01 = (y0 >= 0 && y0 < 64 && x1 >= 0 && x1 < 64) ? 1.f : 0.f;
            float o10 = (y1 >= 0 && y1 < 64 && x0 >= 0 && x0 < 64) ? 1.f : 0.f;
            float o11 = (y1 >= 0 && y1 < 64 && x1 >= 0 && x1 < 64) ? 1.f : 0.f;
            int cy0 = min(max(y0, 0), 63), cx0 = min(max(x0, 0), 63);
            int cy1 = min(max(y1, 0), 63), cx1 = min(max(x1, 0), 63);
            si[0][w] = cy0 * 64 + cx0;  si[1][w] = cy0 * 64 + cx1;
            si[2][w] = cy1 * 64 + cx0;  si[3][w] = cy1 * 64 + cx1;
            sb[0][w] = (1.f - ly) * (1.f - lx) * o00 * m;
            sb[1][w] = (1.f - ly) * lx         * o01 * m;
            sb[2][w] = ly * (1.f - lx)         * o10 * m;
            sb[3][w] = ly * lx                 * o11 * m;
        }
        __syncthreads();

        for (int cc = 0; cc < 2; cc++) {
            int buf = cnt & 1;
            int c0 = ch2 * 64 + cc * 32;
            // stage weights [32 c][128 o] via float4 (4 LDG.128 + 4 STS.128 / thread)
            const float4* wp4 = (const float4*)(g_wT + ((size_t)(g * 9 + k) * 128 + c0) * 128);
            float4* swb4 = (float4*)swt[buf];
#pragma unroll
            for (int i = 0; i < 4; i++) swb4[tid + i * 256] = wp4[tid + i * 256];
            // gather: NHWC float4 loads, 2 tasks per thread
            float* svb = sv[buf];
#pragma unroll
            for (int t = 0; t < 2; t++) {
                int lin = tid + t * 256;       // 512 tasks: (c4, px)
                int c4 = lin >> 6; int px = lin & 63;
                const float4* bp = xT4 + (c0 >> 2) + c4;
                float4 q0 = __ldg(bp + si[0][px] * 32);
                float4 q1 = __ldg(bp + si[1][px] * 32);
                float4 q2 = __ldg(bp + si[2][px] * 32);
                float4 q3 = __ldg(bp + si[3][px] * 32);
                float b0 = sb[0][px], b1 = sb[1][px], b2 = sb[2][px], b3 = sb[3][px];
                float* svp = svb + c4 * 256 + px;
                svp[0]   = b0 * q0.x + b1 * q1.x + b2 * q2.x + b3 * q3.x;
                svp[64]  = b0 * q0.y + b1 * q1.y + b2 * q2.y + b3 * q3.y;
                svp[128] = b0 * q0.z + b1 * q1.z + b2 * q2.z + b3 * q3.z;
                svp[192] = b0 * q0.w + b1 * q1.w + b2 * q2.w + b3 * q3.w;
            }
            __syncthreads();
            float* swb = swt[buf];
            // 8o x 4px FFMA2 register tile over 32-channel chunk
#pragma unroll
            for (int c = 0; c < 32; c++) {
                float4 xa = *(const float4*)&svb[c * 64 + pw * 4];
                unsigned long long xp0 = pack2b(xa.x), xp1 = pack2b(xa.y);
                unsigned long long xp2 = pack2b(xa.z), xp3 = pack2b(xa.w);
                ulonglong2 wv0 = *(const ulonglong2*)&swb[c * 128 + og * 8];
                ulonglong2 wv1 = *(const ulonglong2*)&swb[c * 128 + og * 8 + 4];
                FFMA2(accp[0][0], wv0.x, xp0); FFMA2(accp[0][1], wv0.x, xp1);
                FFMA2(accp[0][2], wv0.x, xp2); FFMA2(accp[0][3], wv0.x, xp3);
                FFMA2(accp[1][0], wv0.y, xp0); FFMA2(accp[1][1], wv0.y, xp1);
                FFMA2(accp[1][2], wv0.y, xp2); FFMA2(accp[1][3], wv0.y, xp3);
                FFMA2(accp[2][0], wv1.x, xp0); FFMA2(accp[2][1], wv1.x, xp1);
                FFMA2(accp[2][2], wv1.x, xp2); FFMA2(accp[2][3], wv1.x, xp3);
                FFMA2(accp[3][0], wv1.y, xp0); FFMA2(accp[3][1], wv1.y, xp1);
                FFMA2(accp[3][2], wv1.y, xp2); FFMA2(accp[3][3], wv1.y, xp3);
            }
            cnt++;
        }
    }

    float* outp = outbuf + ((size_t)(b * 128) * 64 + h) * 64;
#pragma unroll
    for (int op = 0; op < 4; op++)
#pragma unroll
        for (int pi = 0; pi < 4; pi++) {
            float2 f2 = unpack2(accp[op][pi]);
            int o0 = og * 8 + 2 * op;
            outp[(size_t)o0 * NHW + pw * 4 + pi]       = f2.x;
            outp[(size_t)(o0 + 1) * NHW + pw * 4 + pi] = f2.y;
        }
}

// -------- K3: combine 4 deform partials + BN1 stats + fold --------
__global__ __launch_bounds__(256) void k_bn1(const float* __restrict__ gamma,
                                             const float* __restrict__ beta) {
    const size_t N = (size_t)NB * NO * NHW;
    int c = blockIdx.x; int tid = threadIdx.x;
    __shared__ float ssum[256], ssq[256];
    float s = 0.f, sq = 0.f;
    for (int b = 0; b < NB; b++) {
        size_t base = (size_t)(b * 128 + c) * NHW;
        const float4* p0 = (const float4*)(g_out1s + base);
        const float4* p1 = (const float4*)(g_out1s + N + base);
        const float4* p2 = (const float4*)(g_out1s + 2 * N + base);
        const float4* p3 = (const float4*)(g_out1s + 3 * N + base);
        float4* po = (float4*)(g_out1 + base);
        for (int i = tid; i < 1024; i += 256) {
            float4 a = p0[i], bq = p1[i], cq = p2[i], dq = p3[i];
            float4 v = make_float4(a.x + bq.x + cq.x + dq.x, a.y + bq.y + cq.y + dq.y,
                                   a.z + bq.z + cq.z + dq.z, a.w + bq.w + cq.w + dq.w);
            po[i] = v;
            s  += v.x + v.y + v.z + v.w;
            sq += v.x * v.x + v.y * v.y + v.z * v.z + v.w * v.w;
        }
    }
    ssum[tid] = s; ssq[tid] = sq;
    __syncthreads();
    for (int st = 128; st; st >>= 1) {
        if (tid < st) { ssum[tid] += ssum[tid + st]; ssq[tid] += ssq[tid + st]; }
        __syncthreads();
    }
    if (tid == 0) {
        float m  = ssum[0] * (1.f / 16384.f);
        float vv = ssq[0]  * (1.f / 16384.f) - m * m;
        float sc = gamma[c] * rsqrtf(vv + 1e-5f);
        g_scale1[c] = sc;
        g_shift1[c] = beta[c] - m * sc;
    }
}

// -------- K4: conv3x3 (128->128), BN1+ReLU at load, quarter ci split, halo. grid 1024 --------
__global__ __launch_bounds__(256) void k_conv2() {
    int quarter = blockIdx.x >> 8; int rem = blockIdx.x & 255;
    int b = rem >> 6; int h = rem & 63;
    int tid = threadIdx.x; int w = tid & 63; int q = tid >> 6;
    float* outbuf = g_out2s + (size_t)quarter * (NB * NO * NHW);

    __shared__ float sx[8 * 3 * 66];     // halo
    __shared__ float sw[8 * 9 * 128];

    unsigned long long accp[16];
#pragma unroll
    for (int p = 0; p < 16; p++) accp[p] = 0ull;

    for (int ch = 0; ch < 4; ch++) {
        int ci0 = quarter * 32 + ch * 8;
        __syncthreads();
        // weights via float4: 9216 floats = 2304 float4
        const float4* wp4 = (const float4*)(g_wT2 + ci0 * 1152);
        float4* sw4 = (float4*)sw;
        for (int i = tid; i < 2304; i += 256) sw4[i] = wp4[i];
        for (int i = tid; i < 8 * 3 * 66; i += 256) {
            int ci = i / 198; int r2 = i - ci * 198; int r = r2 / 66; int wc = r2 - r * 66;
            int hh = h - 1 + r; int ww = wc - 1; int c = ci0 + ci;
            float v = 0.f;
            if (hh >= 0 && hh < 64 && ww >= 0 && ww < 64) {
                float raw = g_out1[((size_t)(b * 128 + c) * 64 + hh) * 64 + ww];
                v = fmaxf(0.f, raw * g_scale1[c] + g_shift1[c]);
            }
            sx[i] = v;
        }
        __syncthreads();

        for (int ci = 0; ci < 8; ci++) {
#pragma unroll
            for (int kk = 0; kk < 9; kk++) {
                int ky = kk / 3, kx = kk % 3;
                float xval = sx[ci * 198 + ky * 66 + w + kx];   // unconditional
                unsigned long long xb = pack2b(xval);
                const ulonglong2* wrow = (const ulonglong2*)&sw[(ci * 9 + kk) * 128 + q * 32];
#pragma unroll
                for (int j4 = 0; j4 < 8; j4++) {
                    ulonglong2 wv = wrow[j4];
                    FFMA2(accp[2 * j4],     wv.x, xb);
                    FFMA2(accp[2 * j4 + 1], wv.y, xb);
                }
            }
        }
    }

#pragma unroll
    for (int p = 0; p < 16; p++) {
        float2 f2 = unpack2(accp[p]);
        int co = q * 32 + 2 * p;
        outbuf[((size_t)(b * 128 + co) * 64 + h) * 64 + w]     = f2.x;
        outbuf[((size_t)(b * 128 + co + 1) * 64 + h) * 64 + w] = f2.y;
    }
}

// -------- K5: combine 4 conv2 partials + BN2 stats + fold --------
__global__ __launch_bounds__(256) void k_bn2(const float* __restrict__ gamma,
                                             const float* __restrict__ beta) {
    const size_t N = (size_t)NB * NO * NHW;
    int c = blockIdx.x; int tid = threadIdx.x;
    __shared__ float ssum[256], ssq[256];
    float s = 0.f, sq = 0.f;
    for (int b = 0; b < NB; b++) {
        size_t base = (size_t)(b * 128 + c) * NHW;
        const float4* p0 = (const float4*)(g_out2s + base);
        const float4* p1 = (const float4*)(g_out2s + N + base);
        const float4* p2 = (const float4*)(g_out2s + 2 * N + base);
        const float4* p3 = (const float4*)(g_out2s + 3 * N + base);
        float4* po = (float4*)(g_out2 + base);
        for (int i = tid; i < 1024; i += 256) {
            float4 a = p0[i], bq = p1[i], cq = p2[i], dq = p3[i];
            float4 v = make_float4(a.x + bq.x + cq.x + dq.x, a.y + bq.y + cq.y + dq.y,
                                   a.z + bq.z + cq.z + dq.z, a.w + bq.w + cq.w + dq.w);
            po[i] = v;
            s  += v.x + v.y + v.z + v.w;
            sq += v.x * v.x + v.y * v.y + v.z * v.z + v.w * v.w;
        }
    }
    ssum[tid] = s; ssq[tid] = sq;
    __syncthreads();
    for (int st = 128; st; st >>= 1) {
        if (tid < st) { ssum[tid] += ssum[tid + st]; ssq[tid] += ssq[tid + st]; }
        __syncthreads();
    }
    if (tid == 0) {
        float m  = ssum[0] * (1.f / 16384.f);
        float vv = ssq[0]  * (1.f / 16384.f) - m * m;
        float sc = gamma[c] * rsqrtf(vv + 1e-5f);
        g_scale2[c] = sc;
        g_shift2[c] = beta[c] - m * sc;
    }
}

// -------- K6: final BN2 + ReLU elementwise into d_out --------
__global__ void k_final(float* __restrict__ out) {
    int idx = blockIdx.x * 256 + threadIdx.x;
    const float4* in4 = (const float4*)g_out2;
    float4 v = in4[idx];
    int c = (idx >> 10) & 127;
    float sc = g_scale2[c], sh = g_shift2[c];
    float4 r;
    r.x = fmaxf(0.f, v.x * sc + sh);
    r.y = fmaxf(0.f, v.y * sc + sh);
    r.z = fmaxf(0.f, v.z * sc + sh);
    r.w = fmaxf(0.f, v.w * sc + sh);
    ((float4*)out)[idx] = r;
}

// -------- host launcher (graph-capturable) --------
extern "C" void kernel_launch(void* const* d_in, const int* in_sizes, int n_in,
                              void* d_out, int out_size) {
    const float* input_v = (const float*)d_in[0];
    const float* input_i = (const float*)d_in[1];
    const float* off_w   = (const float*)d_in[2];
    const float* off_b   = (const float*)d_in[3];
    const float* dconv_w = (const float*)d_in[4];
    const float* bn1_g   = (const float*)d_in[5];
    const float* bn1_b   = (const float*)d_in[6];
    const float* conv2_w = (const float*)d_in[7];
    const float* bn2_g   = (const float*)d_in[8];
    const float* bn2_b   = (const float*)d_in[9];
    float* out = (float*)d_out;

    k_transpose<<<2214, 256>>>(dconv_w, off_w, conv2_w);
    k_nhwc<<<1024, 256>>>(input_v, input_i);
    k_offconv<<<1024, 256>>>(input_v, input_i);
    k_offpost<<<3456, 256>>>(off_b);
    k_deform<<<1024, 256>>>();
    k_bn1<<<128, 256>>>(bn1_g, bn1_b);
    k_conv2<<<1024, 256>>>();
    k_bn2<<<128, 256>>>(bn2_g, bn2_b);
    k_final<<<2048, 256>>>(out);
}

// round 11
// speedup vs baseline: 1.5773x; 1.1527x over previous
#include <cuda_runtime.h>
#include <math.h>
#include <stdint.h>

#define NB   4
#define CM   128
#define CTOT 256
#define NO   128
#define NH   64
#define NW   64
#define NHW  4096
#define OFFC 54

// ---- packed f32x2 helpers (Blackwell FFMA2 path) ----
#define FFMA2(d, a, b) asm("fma.rn.f32x2 %0, %1, %2, %0;" : "+l"(d) : "l"(a), "l"(b))
__device__ __forceinline__ unsigned long long pack2b(float x) {
    unsigned long long r; asm("mov.b64 %0, {%1, %1};" : "=l"(r) : "f"(x)); return r;
}
__device__ __forceinline__ float2 unpack2(unsigned long long v) {
    float2 f; asm("mov.b64 {%0, %1}, %2;" : "=f"(f.x), "=f"(f.y) : "l"(v)); return f;
}

// -------- device scratch --------
__device__ float g_off  [NB*OFFC*NHW];
__device__ float g_offs [4*NB*OFFC*NHW];       // offconv quarter partials
__device__ float g_xT   [8*4096*128];          // NHWC input: [b*2+g][pos][c]
__device__ float g_wT   [2*9*128*128];         // dconv_w: [g][k][c][o]
__device__ float g_wT1  [CTOT*9*OFFC];         // off_w:   [ci][kk][co]
__device__ float g_wT2  [NO*9*NO];             // conv2_w: [ci][kk][co]
__device__ float g_out1 [NB*NO*NHW];
__device__ float g_out1s[4*NB*NO*NHW];         // deform partials (g x chalf)
__device__ float g_out2 [NB*NO*NHW];
__device__ float g_out2s[4*NB*NO*NHW];         // conv2 quarter partials
__device__ float g_scale1[NO], g_shift1[NO], g_scale2[NO], g_shift2[NO];

// -------- K0: transpose all weights --------
__global__ void k_transpose(const float* __restrict__ dconv_w,
                            const float* __restrict__ off_w,
                            const float* __restrict__ conv2_w) {
    int idx = blockIdx.x * 256 + threadIdx.x;
    if (idx < 294912) {
        int o = idx & 127; int c = (idx >> 7) & 127; int gk = idx >> 14;
        int k = gk % 9; int g = gk / 9;
        g_wT[idx] = dconv_w[(o * 256 + g * 128 + c) * 9 + k];
    } else if (idx < 294912 + 124416) {
        int j = idx - 294912;
        int co = j % 54; int a = j / 54; int ci = a / 9; int kk = a % 9;
        g_wT1[j] = off_w[(co * 256 + ci) * 9 + kk];
    } else if (idx < 294912 + 124416 + 147456) {
        int j = idx - 419328;
        int co = j & 127; int a = j >> 7; int ci = a / 9; int kk = a % 9;
        g_wT2[j] = conv2_w[(co * 128 + ci) * 9 + kk];
    }
}

// -------- K0b: NCHW -> NHWC transpose of inputs --------
__global__ __launch_bounds__(256) void k_nhwc(const float* __restrict__ xv,
                                              const float* __restrict__ xi) {
    int bg = blockIdx.x >> 7; int tile = blockIdx.x & 127;
    int g = bg & 1; int b = bg >> 1;
    int pos0 = tile * 32;
    int tid = threadIdx.x;
    const float* src = (g ? xi : xv) + (size_t)b * 128 * NHW;
    __shared__ float s[128][33];
#pragma unroll
    for (int it = 0; it < 16; it++) {
        int i = tid + it * 256;
        int c = i >> 5; int p = i & 31;
        s[c][p] = src[(size_t)c * NHW + pos0 + p];
    }
    __syncthreads();
    float* dst = g_xT + ((size_t)bg * 4096 + pos0) * 128;
#pragma unroll
    for (int it = 0; it < 16; it++) {
        int j = tid + it * 256;
        int p = j >> 7; int c = j & 127;
        dst[(size_t)p * 128 + c] = s[c][p];
    }
}

// -------- K1: offset conv3x3, quarter ci split, 2 h-rows per CTA. grid 512 --------
__global__ __launch_bounds__(256) void k_offconv(const float* __restrict__ xv,
                                                 const float* __restrict__ xi) {
    int quarter = blockIdx.x >> 7; int rem = blockIdx.x & 127;
    int b = rem >> 5; int hp = rem & 31; int h0 = hp * 2;
    int tid = threadIdx.x; int w = tid & 63; int q = tid >> 6;
    const float* xsrc = (quarter < 2) ? xv : xi;
    float* outbuf = g_offs + (size_t)quarter * (NB * OFFC * NHW);

    __shared__ float sx[16 * 4 * 66];          // 4 halo rows per 2 output rows
    __shared__ float sw[16 * 9 * 4 * 16];

    unsigned long long accp[2][8];             // [row][pair]
#pragma unroll
    for (int r = 0; r < 2; r++)
#pragma unroll
        for (int p = 0; p < 8; p++) accp[r][p] = 0ull;

    for (int ch = 0; ch < 4; ch++) {
        int ci0 = quarter * 64 + ch * 16;
        int cl0 = (quarter & 1) * 64 + ch * 16;
        __syncthreads();
        for (int i = tid; i < 16 * 9 * 4 * 2; i += 256) {
            int j = 14 + (i & 1); int aq = i >> 1;
            sw[aq * 16 + j] = 0.f;
        }
        for (int i = tid; i < 16 * 9 * 54; i += 256) {
            int a = i / 54; int co = i - a * 54;
            sw[(a * 4 + (co & 3)) * 16 + (co >> 2)] = g_wT1[ci0 * (9 * 54) + i];
        }
        for (int i = tid; i < 16 * 4 * 66; i += 256) {
            int ci = i / 264; int r2 = i - ci * 264; int r = r2 / 66; int wc = r2 - r * 66;
            int hh = h0 - 1 + r; int ww = wc - 1;
            float v = 0.f;
            if (hh >= 0 && hh < 64 && ww >= 0 && ww < 64)
                v = xsrc[((size_t)(b * 128 + cl0 + ci) * 64 + hh) * 64 + ww];
            sx[i] = v;
        }
        __syncthreads();

        for (int ci = 0; ci < 16; ci++) {
#pragma unroll
            for (int kk = 0; kk < 9; kk++) {
                int kx = kk % 3, ky = kk / 3;
                float x0 = sx[ci * 264 + ky * 66 + w + kx];
                float x1 = sx[ci * 264 + (ky + 1) * 66 + w + kx];
                unsigned long long xb0 = pack2b(x0);
                unsigned long long xb1 = pack2b(x1);
                const ulonglong2* wrow = (const ulonglong2*)&sw[((ci * 9 + kk) * 4 + q) * 16];
#pragma unroll
                for (int j4 = 0; j4 < 4; j4++) {
                    ulonglong2 wv = wrow[j4];
                    FFMA2(accp[0][2 * j4],     wv.x, xb0);
                    FFMA2(accp[0][2 * j4 + 1], wv.y, xb0);
                    FFMA2(accp[1][2 * j4],     wv.x, xb1);
                    FFMA2(accp[1][2 * j4 + 1], wv.y, xb1);
                }
            }
        }
    }

#pragma unroll
    for (int r = 0; r < 2; r++) {
        int h = h0 + r;
#pragma unroll
        for (int p = 0; p < 8; p++) {
            float2 f2 = unpack2(accp[r][p]);
            int j0 = (p >> 1) * 4 + (p & 1) * 2;
#pragma unroll
            for (int s = 0; s < 2; s++) {
                int co = q + 4 * (j0 + s);
                if (co < 54)
                    outbuf[((size_t)(b * 54 + co) * 64 + h) * 64 + w] = (s == 0 ? f2.x : f2.y);
            }
        }
    }
}

// -------- K1b: combine 4 quarters + bias + sigmoid --------
__global__ void k_offpost(const float* __restrict__ off_b) {
    const int N = NB * OFFC * NHW;
    int idx = blockIdx.x * 256 + threadIdx.x;
    int co = (idx >> 12) % 54;
    float v = g_offs[idx] + g_offs[N + idx] + g_offs[2 * N + idx] + g_offs[3 * N + idx]
            + off_b[co];
    if (co >= 36) v = 1.f / (1.f + expf(-v));
    g_off[idx] = v;
}

// -------- K2: deform-sample + grouped GEMM, split by (g, c-half). grid 1024 --------
__global__ __launch_bounds__(256) void k_deform() {
    int bx = blockIdx.x;
    int ch2 = bx >> 9;              // c-half
    int g   = (bx >> 8) & 1;
    int b   = (bx >> 6) & 3;
    int h   = bx & 63;
    int tid = threadIdx.x;
    int og = tid >> 4; int pw = tid & 15;
    float* outbuf = g_out1s + (size_t)(g * 2 + ch2) * (NB * NO * NHW);
    const float4* xT4 = (const float4*)g_xT + (size_t)(b * 2 + g) * 4096 * 32;

    __shared__ float sv [2][2048];     // [buf][32 c][64 px]
    __shared__ float swt[2][4096];     // [buf][32 c][128 o]
    __shared__ int   si[4][64];
    __shared__ float sb[4][64];

    unsigned long long accp[4][4];
#pragma unroll
    for (int op = 0; op < 4; op++)
#pragma unroll
        for (int pi = 0; pi < 4; pi++) accp[op][pi] = 0ull;

    int cnt = 0;
    for (int k = 0; k < 9; k++) {
        int ky = k / 3 - 1, kx = (k % 3) - 1;
        __syncthreads();
        if (tid < 64) {
            int w = tid;
            const float* offp = g_off + (size_t)b * 54 * NHW + h * 64 + w;
            float dy = offp[(size_t)(g * 18 + 2 * k) * NHW];
            float dx = offp[(size_t)(g * 18 + 2 * k + 1) * NHW];
            float m  = offp[(size_t)(36 + g * 9 + k) * NHW];
            float py = dy + (float)(h + ky);
            float px = dx + (float)(w + kx);
            float fy = floorf(py), fx = floorf(px);
            float ly = py - fy,   lx = px - fx;
            int y0 = (int)fy, x0 = (int)fx;
            int y1 = y0 + 1,  x1 = x0 + 1;
            float o00 = (y0 >= 0 && y0 < 64 && x0 >= 0 && x0 < 64) ? 1.f : 0.f;
            float o01 = (y0 >= 0 && y0 < 64 && x1 >= 0 && x1 < 64) ? 1.f : 0.f;
            float o10 = (y1 >= 0 && y1 < 64 && x0 >= 0 && x0 < 64) ? 1.f : 0.f;
            float o11 = (y1 >= 0 && y1 < 64 && x1 >= 0 && x1 < 64) ? 1.f : 0.f;
            int cy0 = min(max(y0, 0), 63), cx0 = min(max(x0, 0), 63);
            int cy1 = min(max(y1, 0), 63), cx1 = min(max(x1, 0), 63);
            si[0][w] = cy0 * 64 + cx0;  si[1][w] = cy0 * 64 + cx1;
            si[2][w] = cy1 * 64 + cx0;  si[3][w] = cy1 * 64 + cx1;
            sb[0][w] = (1.f - ly) * (1.f - lx) * o00 * m;
            sb[1][w] = (1.f - ly) * lx         * o01 * m;
            sb[2][w] = ly * (1.f - lx)         * o10 * m;
            sb[3][w] = ly * lx                 * o11 * m;
        }
        __syncthreads();

        for (int cc = 0; cc < 2; cc++) {
            int buf = cnt & 1;
            int c0 = ch2 * 64 + cc * 32;
            const float4* wp4 = (const float4*)(g_wT + ((size_t)(g * 9 + k) * 128 + c0) * 128);
            float4* swb4 = (float4*)swt[buf];
#pragma unroll
            for (int i = 0; i < 4; i++) swb4[tid + i * 256] = wp4[tid + i * 256];
            float* svb = sv[buf];
#pragma unroll
            for (int t = 0; t < 2; t++) {
                int lin = tid + t * 256;
                int c4 = lin >> 6; int px = lin & 63;
                const float4* bp = xT4 + (c0 >> 2) + c4;
                float4 q0 = __ldg(bp + si[0][px] * 32);
                float4 q1 = __ldg(bp + si[1][px] * 32);
                float4 q2 = __ldg(bp + si[2][px] * 32);
                float4 q3 = __ldg(bp + si[3][px] * 32);
                float b0 = sb[0][px], b1 = sb[1][px], b2 = sb[2][px], b3 = sb[3][px];
                float* svp = svb + c4 * 256 + px;
                svp[0]   = b0 * q0.x + b1 * q1.x + b2 * q2.x + b3 * q3.x;
                svp[64]  = b0 * q0.y + b1 * q1.y + b2 * q2.y + b3 * q3.y;
                svp[128] = b0 * q0.z + b1 * q1.z + b2 * q2.z + b3 * q3.z;
                svp[192] = b0 * q0.w + b1 * q1.w + b2 * q2.w + b3 * q3.w;
            }
            __syncthreads();
            float* swb = swt[buf];
#pragma unroll
            for (int c = 0; c < 32; c++) {
                float4 xa = *(const float4*)&svb[c * 64 + pw * 4];
                unsigned long long xp0 = pack2b(xa.x), xp1 = pack2b(xa.y);
                unsigned long long xp2 = pack2b(xa.z), xp3 = pack2b(xa.w);
                ulonglong2 wv0 = *(const ulonglong2*)&swb[c * 128 + og * 8];
                ulonglong2 wv1 = *(const ulonglong2*)&swb[c * 128 + og * 8 + 4];
                FFMA2(accp[0][0], wv0.x, xp0); FFMA2(accp[0][1], wv0.x, xp1);
                FFMA2(accp[0][2], wv0.x, xp2); FFMA2(accp[0][3], wv0.x, xp3);
                FFMA2(accp[1][0], wv0.y, xp0); FFMA2(accp[1][1], wv0.y, xp1);
                FFMA2(accp[1][2], wv0.y, xp2); FFMA2(accp[1][3], wv0.y, xp3);
                FFMA2(accp[2][0], wv1.x, xp0); FFMA2(accp[2][1], wv1.x, xp1);
                FFMA2(accp[2][2], wv1.x, xp2); FFMA2(accp[2][3], wv1.x, xp3);
                FFMA2(accp[3][0], wv1.y, xp0); FFMA2(accp[3][1], wv1.y, xp1);
                FFMA2(accp[3][2], wv1.y, xp2); FFMA2(accp[3][3], wv1.y, xp3);
            }
            cnt++;
        }
    }

    // epilogue: float4 stores (px contiguous per o row)
    float* outp = outbuf + ((size_t)(b * 128) * 64 + h) * 64;
#pragma unroll
    for (int op = 0; op < 4; op++) {
        float2 a0 = unpack2(accp[op][0]);
        float2 a1 = unpack2(accp[op][1]);
        float2 a2 = unpack2(accp[op][2]);
        float2 a3 = unpack2(accp[op][3]);
        int o0 = og * 8 + 2 * op;
        *(float4*)(outp + (size_t)o0 * NHW + pw * 4)       = make_float4(a0.x, a1.x, a2.x, a3.x);
        *(float4*)(outp + (size_t)(o0 + 1) * NHW + pw * 4) = make_float4(a0.y, a1.y, a2.y, a3.y);
    }
}

// -------- K3: combine 4 deform partials + BN1 stats + fold --------
__global__ __launch_bounds__(256) void k_bn1(const float* __restrict__ gamma,
                                             const float* __restrict__ beta) {
    const size_t N = (size_t)NB * NO * NHW;
    int c = blockIdx.x; int tid = threadIdx.x;
    __shared__ float ssum[256], ssq[256];
    float s = 0.f, sq = 0.f;
    for (int b = 0; b < NB; b++) {
        size_t base = (size_t)(b * 128 + c) * NHW;
        const float4* p0 = (const float4*)(g_out1s + base);
        const float4* p1 = (const float4*)(g_out1s + N + base);
        const float4* p2 = (const float4*)(g_out1s + 2 * N + base);
        const float4* p3 = (const float4*)(g_out1s + 3 * N + base);
        float4* po = (float4*)(g_out1 + base);
        for (int i = tid; i < 1024; i += 256) {
            float4 a = p0[i], bq = p1[i], cq = p2[i], dq = p3[i];
            float4 v = make_float4(a.x + bq.x + cq.x + dq.x, a.y + bq.y + cq.y + dq.y,
                                   a.z + bq.z + cq.z + dq.z, a.w + bq.w + cq.w + dq.w);
            po[i] = v;
            s  += v.x + v.y + v.z + v.w;
            sq += v.x * v.x + v.y * v.y + v.z * v.z + v.w * v.w;
        }
    }
    ssum[tid] = s; ssq[tid] = sq;
    __syncthreads();
    for (int st = 128; st; st >>= 1) {
        if (tid < st) { ssum[tid] += ssum[tid + st]; ssq[tid] += ssq[tid + st]; }
        __syncthreads();
    }
    if (tid == 0) {
        float m  = ssum[0] * (1.f / 16384.f);
        float vv = ssq[0]  * (1.f / 16384.f) - m * m;
        float sc = gamma[c] * rsqrtf(vv + 1e-5f);
        g_scale1[c] = sc;
        g_shift1[c] = beta[c] - m * sc;
    }
}

// -------- K4: conv3x3 (128->128), BN1+ReLU at load, quarter ci x co-half x h-pair. grid 1024 --------
__global__ __launch_bounds__(256) void k_conv2() {
    int quarter = blockIdx.x >> 8;
    int rem = blockIdx.x & 255;
    int cohalf = rem >> 7;
    int rem2 = rem & 127;
    int b = rem2 >> 5; int hp = rem2 & 31; int h0 = hp * 2;
    int tid = threadIdx.x; int w = tid & 63; int q = tid >> 6;
    float* outbuf = g_out2s + (size_t)quarter * (NB * NO * NHW);
    int co_base = cohalf * 64 + q * 16;

    __shared__ float sx[8 * 4 * 66];      // 4 halo rows
    __shared__ float sw[8 * 9 * 64];      // co-half slice

    unsigned long long accp[2][8];        // [row][pair]  (16 co)
#pragma unroll
    for (int r = 0; r < 2; r++)
#pragma unroll
        for (int p = 0; p < 8; p++) accp[r][p] = 0ull;

    for (int ch = 0; ch < 4; ch++) {
        int ci0 = quarter * 32 + ch * 8;
        __syncthreads();
        // weights: co-half slice, float4 (8ci*9kk*64co = 4608 floats = 1152 float4)
        float4* sw4 = (float4*)sw;
        for (int i = tid; i < 1152; i += 256) {
            int a = i >> 4; int j = i & 15;     // a = ci*9+kk, j = co-float4 within 64
            sw4[i] = *(const float4*)(g_wT2 + (size_t)(ci0 * 9 + a) * 128 + cohalf * 64 + j * 4);
        }
        for (int i = tid; i < 8 * 4 * 66; i += 256) {
            int ci = i / 264; int r2 = i - ci * 264; int r = r2 / 66; int wc = r2 - r * 66;
            int hh = h0 - 1 + r; int ww = wc - 1; int c = ci0 + ci;
            float v = 0.f;
            if (hh >= 0 && hh < 64 && ww >= 0 && ww < 64) {
                float raw = g_out1[((size_t)(b * 128 + c) * 64 + hh) * 64 + ww];
                v = fmaxf(0.f, raw * g_scale1[c] + g_shift1[c]);
            }
            sx[i] = v;
        }
        __syncthreads();

        for (int ci = 0; ci < 8; ci++) {
#pragma unroll
            for (int kk = 0; kk < 9; kk++) {
                int ky = kk / 3, kx = kk % 3;
                float x0 = sx[ci * 264 + ky * 66 + w + kx];
                float x1 = sx[ci * 264 + (ky + 1) * 66 + w + kx];
                unsigned long long xb0 = pack2b(x0);
                unsigned long long xb1 = pack2b(x1);
                const ulonglong2* wrow = (const ulonglong2*)&sw[(ci * 9 + kk) * 64 + q * 16];
#pragma unroll
                for (int j4 = 0; j4 < 4; j4++) {
                    ulonglong2 wv = wrow[j4];
                    FFMA2(accp[0][2 * j4],     wv.x, xb0);
                    FFMA2(accp[0][2 * j4 + 1], wv.y, xb0);
                    FFMA2(accp[1][2 * j4],     wv.x, xb1);
                    FFMA2(accp[1][2 * j4 + 1], wv.y, xb1);
                }
            }
        }
    }

#pragma unroll
    for (int r = 0; r < 2; r++) {
        int h = h0 + r;
#pragma unroll
        for (int p = 0; p < 8; p++) {
            float2 f2 = unpack2(accp[r][p]);
            int co = co_base + 2 * p;
            outbuf[((size_t)(b * 128 + co) * 64 + h) * 64 + w]     = f2.x;
            outbuf[((size_t)(b * 128 + co + 1) * 64 + h) * 64 + w] = f2.y;
        }
    }
}

// -------- K5: combine 4 conv2 partials + BN2 stats + fold --------
__global__ __launch_bounds__(256) void k_bn2(const float* __restrict__ gamma,
                                             const float* __restrict__ beta) {
    const size_t N = (size_t)NB * NO * NHW;
    int c = blockIdx.x; int tid = threadIdx.x;
    __shared__ float ssum[256], ssq[256];
    float s = 0.f, sq = 0.f;
    for (int b = 0; b < NB; b++) {
        size_t base = (size_t)(b * 128 + c) * NHW;
        const float4* p0 = (const float4*)(g_out2s + base);
        const float4* p1 = (const float4*)(g_out2s + N + base);
        const float4* p2 = (const float4*)(g_out2s + 2 * N + base);
        const float4* p3 = (const float4*)(g_out2s + 3 * N + base);
        float4* po = (float4*)(g_out2 + base);
        for (int i = tid; i < 1024; i += 256) {
            float4 a = p0[i], bq = p1[i], cq = p2[i], dq = p3[i];
            float4 v = make_float4(a.x + bq.x + cq.x + dq.x, a.y + bq.y + cq.y + dq.y,
                                   a.z + bq.z + cq.z + dq.z, a.w + bq.w + cq.w + dq.w);
            po[i] = v;
            s  += v.x + v.y + v.z + v.w;
            sq += v.x * v.x + v.y * v.y + v.z * v.z + v.w * v.w;
        }
    }
    ssum[tid] = s; ssq[tid] = sq;
    __syncthreads();
    for (int st = 128; st; st >>= 1) {
        if (tid < st) { ssum[tid] += ssum[tid + st]; ssq[tid] += ssq[tid + st]; }
        __syncthreads();
    }
    if (tid == 0) {
        float m  = ssum[0] * (1.f / 16384.f);
        float vv = ssq[0]  * (1.f / 16384.f) - m * m;
        float sc = gamma[c] * rsqrtf(vv + 1e-5f);
        g_scale2[c] = sc;
        g_shift2[c] = beta[c] - m * sc;
    }
}

// -------- K6: final BN2 + ReLU elementwise into d_out --------
__global__ void k_final(float* __restrict__ out) {
    int idx = blockIdx.x * 256 + threadIdx.x;
    const float4* in4 = (const float4*)g_out2;
    float4 v = in4[idx];
    int c = (idx >> 10) & 127;
    float sc = g_scale2[c], sh = g_shift2[c];
    float4 r;
    r.x = fmaxf(0.f, v.x * sc + sh);
    r.y = fmaxf(0.f, v.y * sc + sh);
    r.z = fmaxf(0.f, v.z * sc + sh);
    r.w = fmaxf(0.f, v.w * sc + sh);
    ((float4*)out)[idx] = r;
}

// -------- host launcher (graph-capturable) --------
extern "C" void kernel_launch(void* const* d_in, const int* in_sizes, int n_in,
                              void* d_out, int out_size) {
    const float* input_v = (const float*)d_in[0];
    const float* input_i = (const float*)d_in[1];
    const float* off_w   = (const float*)d_in[2];
    const float* off_b   = (const float*)d_in[3];
    const float* dconv_w = (const float*)d_in[4];
    const float* bn1_g   = (const float*)d_in[5];
    const float* bn1_b   = (const float*)d_in[6];
    const float* conv2_w = (const float*)d_in[7];
    const float* bn2_g   = (const float*)d_in[8];
    const float* bn2_b   = (const float*)d_in[9];
    float* out = (float*)d_out;

    k_transpose<<<2214, 256>>>(dconv_w, off_w, conv2_w);
    k_nhwc<<<1024, 256>>>(input_v, input_i);
    k_offconv<<<512, 256>>>(input_v, input_i);
    k_offpost<<<3456, 256>>>(off_b);
    k_deform<<<1024, 256>>>();
    k_bn1<<<128, 256>>>(bn1_g, bn1_b);
    k_conv2<<<1024, 256>>>();
    k_bn2<<<128, 256>>>(bn2_g, bn2_b);
    k_final<<<2048, 256>>>(out);
}

// round 12
// speedup vs baseline: 1.6007x; 1.0149x over previous
#include <cuda_runtime.h>
#include <math.h>
#include <stdint.h>

#define NB   4
#define CM   128
#define CTOT 256
#define NO   128
#define NH   64
#define NW   64
#define NHW  4096
#define OFFC 54

// ---- packed f32x2 helpers (Blackwell FFMA2 path) ----
#define FFMA2(d, a, b) asm("fma.rn.f32x2 %0, %1, %2, %0;" : "+l"(d) : "l"(a), "l"(b))
__device__ __forceinline__ unsigned long long pack2b(float x) {
    unsigned long long r; asm("mov.b64 %0, {%1, %1};" : "=l"(r) : "f"(x)); return r;
}
__device__ __forceinline__ float2 unpack2(unsigned long long v) {
    float2 f; asm("mov.b64 {%0, %1}, %2;" : "=f"(f.x), "=f"(f.y) : "l"(v)); return f;
}

// -------- device scratch --------
__device__ float g_off  [NB*OFFC*NHW];
__device__ float g_offs [4*NB*OFFC*NHW];       // offconv quarter partials
__device__ float g_xT   [8*4096*128];          // NHWC input: [b*2+g][pos][c]
__device__ float g_wT   [2*9*128*128];         // dconv_w: [g][k][c][o]
__device__ float g_wT1  [CTOT*9*OFFC];         // off_w:   [ci][kk][co]
__device__ float g_wT2  [NO*9*NO];             // conv2_w: [ci][kk][co]
__device__ float g_out1 [NB*NO*NHW];
__device__ float g_out1s[4*NB*NO*NHW];         // deform partials (g x chalf)
__device__ float g_out2 [NB*NO*NHW];
__device__ float g_out2s[4*NB*NO*NHW];         // conv2 quarter partials
__device__ float g_scale1[NO], g_shift1[NO], g_scale2[NO], g_shift2[NO];

// -------- K0: merged weight transpose + NCHW->NHWC input transpose --------
__global__ __launch_bounds__(256) void k_prep(const float* __restrict__ dconv_w,
                                              const float* __restrict__ off_w,
                                              const float* __restrict__ conv2_w,
                                              const float* __restrict__ xv,
                                              const float* __restrict__ xi) {
    __shared__ float s[128][33];
    int tid = threadIdx.x;
    if (blockIdx.x < 2214) {
        int idx = blockIdx.x * 256 + tid;
        if (idx < 294912) {
            int o = idx & 127; int c = (idx >> 7) & 127; int gk = idx >> 14;
            int k = gk % 9; int g = gk / 9;
            g_wT[idx] = dconv_w[(o * 256 + g * 128 + c) * 9 + k];
        } else if (idx < 294912 + 124416) {
            int j = idx - 294912;
            int co = j % 54; int a = j / 54; int ci = a / 9; int kk = a % 9;
            g_wT1[j] = off_w[(co * 256 + ci) * 9 + kk];
        } else if (idx < 294912 + 124416 + 147456) {
            int j = idx - 419328;
            int co = j & 127; int a = j >> 7; int ci = a / 9; int kk = a % 9;
            g_wT2[j] = conv2_w[(co * 128 + ci) * 9 + kk];
        }
    } else {
        int bx = blockIdx.x - 2214;
        int bg = bx >> 7; int tile = bx & 127;
        int g = bg & 1; int b = bg >> 1;
        int pos0 = tile * 32;
        const float* src = (g ? xi : xv) + (size_t)b * 128 * NHW;
#pragma unroll
        for (int it = 0; it < 16; it++) {
            int i = tid + it * 256;
            int c = i >> 5; int p = i & 31;
            s[c][p] = src[(size_t)c * NHW + pos0 + p];
        }
        __syncthreads();
        float* dst = g_xT + ((size_t)bg * 4096 + pos0) * 128;
#pragma unroll
        for (int it = 0; it < 16; it++) {
            int j = tid + it * 256;
            int p = j >> 7; int c = j & 127;
            dst[(size_t)p * 128 + c] = s[c][p];
        }
    }
}

// -------- K1: offset conv3x3, quarter ci split, 2 h-rows per CTA. grid 512 --------
__global__ __launch_bounds__(256) void k_offconv(const float* __restrict__ xv,
                                                 const float* __restrict__ xi) {
    int quarter = blockIdx.x >> 7; int rem = blockIdx.x & 127;
    int b = rem >> 5; int hp = rem & 31; int h0 = hp * 2;
    int tid = threadIdx.x; int w = tid & 63; int q = tid >> 6;
    const float* xsrc = (quarter < 2) ? xv : xi;
    float* outbuf = g_offs + (size_t)quarter * (NB * OFFC * NHW);

    __shared__ float sx[16 * 4 * 66];
    __shared__ float sw[16 * 9 * 4 * 16];

    unsigned long long accp[2][8];
#pragma unroll
    for (int r = 0; r < 2; r++)
#pragma unroll
        for (int p = 0; p < 8; p++) accp[r][p] = 0ull;

    for (int ch = 0; ch < 4; ch++) {
        int ci0 = quarter * 64 + ch * 16;
        int cl0 = (quarter & 1) * 64 + ch * 16;
        __syncthreads();
        for (int i = tid; i < 16 * 9 * 4 * 2; i += 256) {
            int j = 14 + (i & 1); int aq = i >> 1;
            sw[aq * 16 + j] = 0.f;
        }
        for (int i = tid; i < 16 * 9 * 54; i += 256) {
            int a = i / 54; int co = i - a * 54;
            sw[(a * 4 + (co & 3)) * 16 + (co >> 2)] = g_wT1[ci0 * (9 * 54) + i];
        }
        for (int i = tid; i < 16 * 4 * 66; i += 256) {
            int ci = i / 264; int r2 = i - ci * 264; int r = r2 / 66; int wc = r2 - r * 66;
            int hh = h0 - 1 + r; int ww = wc - 1;
            float v = 0.f;
            if (hh >= 0 && hh < 64 && ww >= 0 && ww < 64)
                v = xsrc[((size_t)(b * 128 + cl0 + ci) * 64 + hh) * 64 + ww];
            sx[i] = v;
        }
        __syncthreads();

        for (int ci = 0; ci < 16; ci++) {
#pragma unroll
            for (int kk = 0; kk < 9; kk++) {
                int kx = kk % 3, ky = kk / 3;
                float x0 = sx[ci * 264 + ky * 66 + w + kx];
                float x1 = sx[ci * 264 + (ky + 1) * 66 + w + kx];
                unsigned long long xb0 = pack2b(x0);
                unsigned long long xb1 = pack2b(x1);
                const ulonglong2* wrow = (const ulonglong2*)&sw[((ci * 9 + kk) * 4 + q) * 16];
#pragma unroll
                for (int j4 = 0; j4 < 4; j4++) {
                    ulonglong2 wv = wrow[j4];
                    FFMA2(accp[0][2 * j4],     wv.x, xb0);
                    FFMA2(accp[0][2 * j4 + 1], wv.y, xb0);
                    FFMA2(accp[1][2 * j4],     wv.x, xb1);
                    FFMA2(accp[1][2 * j4 + 1], wv.y, xb1);
                }
            }
        }
    }

#pragma unroll
    for (int r = 0; r < 2; r++) {
        int h = h0 + r;
#pragma unroll
        for (int p = 0; p < 8; p++) {
            float2 f2 = unpack2(accp[r][p]);
            int j0 = (p >> 1) * 4 + (p & 1) * 2;
#pragma unroll
            for (int s = 0; s < 2; s++) {
                int co = q + 4 * (j0 + s);
                if (co < 54)
                    outbuf[((size_t)(b * 54 + co) * 64 + h) * 64 + w] = (s == 0 ? f2.x : f2.y);
            }
        }
    }
}

// -------- K1b: combine 4 quarters + bias + sigmoid --------
__global__ void k_offpost(const float* __restrict__ off_b) {
    const int N = NB * OFFC * NHW;
    int idx = blockIdx.x * 256 + threadIdx.x;
    int co = (idx >> 12) % 54;
    float v = g_offs[idx] + g_offs[N + idx] + g_offs[2 * N + idx] + g_offs[3 * N + idx]
            + off_b[co];
    if (co >= 36) v = 1.f / (1.f + expf(-v));
    g_off[idx] = v;
}

// -------- K2: deform-sample + grouped GEMM, split by (g, c-half). grid 1024 --------
// Ping-pong si/sb; offsets for tap k+1 computed by ALL threads during chunk 2k+1.
__global__ __launch_bounds__(256) void k_deform() {
    int bx = blockIdx.x;
    int ch2 = bx >> 9;              // c-half
    int g   = (bx >> 8) & 1;
    int b   = (bx >> 6) & 3;
    int h   = bx & 63;
    int tid = threadIdx.x;
    int og = tid >> 4; int pw = tid & 15;
    float* outbuf = g_out1s + (size_t)(g * 2 + ch2) * (NB * NO * NHW);
    const float4* xT4 = (const float4*)g_xT + (size_t)(b * 2 + g) * 4096 * 32;
    const float* offbase = g_off + (size_t)b * 54 * NHW + h * 64;

    __shared__ float sv [2][2048];     // [buf][32 c][64 px]
    __shared__ float swt[2][4096];     // [buf][32 c][128 o]
    __shared__ int   si[2][4][64];     // [parity][corner][px]
    __shared__ float sb[2][4][64];

    // all-thread offset computation for tap k into parity buffer
    auto compute_offsets = [&](int k, int par) {
        int corner = tid >> 6;        // 0..3
        int w = tid & 63;
        int ky = k / 3 - 1, kx = (k % 3) - 1;
        const float* offp = offbase + w;
        float dy = offp[(size_t)(g * 18 + 2 * k) * NHW];
        float dx = offp[(size_t)(g * 18 + 2 * k + 1) * NHW];
        float m  = offp[(size_t)(36 + g * 9 + k) * NHW];
        float py = dy + (float)(h + ky);
        float px = dx + (float)(w + kx);
        float fy = floorf(py), fx = floorf(px);
        float ly = py - fy,   lx = px - fx;
        int y0 = (int)fy, x0 = (int)fx;
        int yc = (corner & 2) ? y0 + 1 : y0;
        int xc = (corner & 1) ? x0 + 1 : x0;
        float ok = (yc >= 0 && yc < 64 && xc >= 0 && xc < 64) ? 1.f : 0.f;
        float wy = (corner & 2) ? ly : 1.f - ly;
        float wx = (corner & 1) ? lx : 1.f - lx;
        int cy = min(max(yc, 0), 63), cx = min(max(xc, 0), 63);
        si[par][corner][w] = cy * 64 + cx;
        sb[par][corner][w] = wy * wx * ok * m;
    };

    unsigned long long accp[4][4];
#pragma unroll
    for (int op = 0; op < 4; op++)
#pragma unroll
        for (int pi = 0; pi < 4; pi++) accp[op][pi] = 0ull;

    compute_offsets(0, 0);
    __syncthreads();

    for (int cnt = 0; cnt < 18; cnt++) {
        int k = cnt >> 1; int cc = cnt & 1; int buf = cnt & 1; int par = k & 1;
        int c0 = ch2 * 64 + cc * 32;
        // stage weights [32 c][128 o] via float4
        const float4* wp4 = (const float4*)(g_wT + ((size_t)(g * 9 + k) * 128 + c0) * 128);
        float4* swb4 = (float4*)swt[buf];
#pragma unroll
        for (int i = 0; i < 4; i++) swb4[tid + i * 256] = wp4[tid + i * 256];
        // gather: NHWC float4 loads
        float* svb = sv[buf];
        const int* sip = &si[par][0][0];
        const float* sbp = &sb[par][0][0];
#pragma unroll
        for (int t = 0; t < 2; t++) {
            int lin = tid + t * 256;
            int c4 = lin >> 6; int px = lin & 63;
            const float4* bp = xT4 + (c0 >> 2) + c4;
            float4 q0 = __ldg(bp + sip[px] * 32);
            float4 q1 = __ldg(bp + sip[64 + px] * 32);
            float4 q2 = __ldg(bp + sip[128 + px] * 32);
            float4 q3 = __ldg(bp + sip[192 + px] * 32);
            float b0 = sbp[px], b1 = sbp[64 + px], b2 = sbp[128 + px], b3 = sbp[192 + px];
            float* svp = svb + c4 * 256 + px;
            svp[0]   = b0 * q0.x + b1 * q1.x + b2 * q2.x + b3 * q3.x;
            svp[64]  = b0 * q0.y + b1 * q1.y + b2 * q2.y + b3 * q3.y;
            svp[128] = b0 * q0.z + b1 * q1.z + b2 * q2.z + b3 * q3.z;
            svp[192] = b0 * q0.w + b1 * q1.w + b2 * q2.w + b3 * q3.w;
        }
        // during odd chunks, compute next tap's offsets into parity^1 (no extra barrier)
        if (cc == 1 && k < 8) compute_offsets(k + 1, par ^ 1);
        __syncthreads();
        float* swb = swt[buf];
#pragma unroll
        for (int c = 0; c < 32; c++) {
            float4 xa = *(const float4*)&svb[c * 64 + pw * 4];
            unsigned long long xp0 = pack2b(xa.x), xp1 = pack2b(xa.y);
            unsigned long long xp2 = pack2b(xa.z), xp3 = pack2b(xa.w);
            ulonglong2 wv0 = *(const ulonglong2*)&swb[c * 128 + og * 8];
            ulonglong2 wv1 = *(const ulonglong2*)&swb[c * 128 + og * 8 + 4];
            FFMA2(accp[0][0], wv0.x, xp0); FFMA2(accp[0][1], wv0.x, xp1);
            FFMA2(accp[0][2], wv0.x, xp2); FFMA2(accp[0][3], wv0.x, xp3);
            FFMA2(accp[1][0], wv0.y, xp0); FFMA2(accp[1][1], wv0.y, xp1);
            FFMA2(accp[1][2], wv0.y, xp2); FFMA2(accp[1][3], wv0.y, xp3);
            FFMA2(accp[2][0], wv1.x, xp0); FFMA2(accp[2][1], wv1.x, xp1);
            FFMA2(accp[2][2], wv1.x, xp2); FFMA2(accp[2][3], wv1.x, xp3);
            FFMA2(accp[3][0], wv1.y, xp0); FFMA2(accp[3][1], wv1.y, xp1);
            FFMA2(accp[3][2], wv1.y, xp2); FFMA2(accp[3][3], wv1.y, xp3);
        }
    }

    // epilogue: float4 stores
    float* outp = outbuf + ((size_t)(b * 128) * 64 + h) * 64;
#pragma unroll
    for (int op = 0; op < 4; op++) {
        float2 a0 = unpack2(accp[op][0]);
        float2 a1 = unpack2(accp[op][1]);
        float2 a2 = unpack2(accp[op][2]);
        float2 a3 = unpack2(accp[op][3]);
        int o0 = og * 8 + 2 * op;
        *(float4*)(outp + (size_t)o0 * NHW + pw * 4)       = make_float4(a0.x, a1.x, a2.x, a3.x);
        *(float4*)(outp + (size_t)(o0 + 1) * NHW + pw * 4) = make_float4(a0.y, a1.y, a2.y, a3.y);
    }
}

// -------- K3: combine 4 deform partials + BN1 stats + fold --------
__global__ __launch_bounds__(256) void k_bn1(const float* __restrict__ gamma,
                                             const float* __restrict__ beta) {
    const size_t N = (size_t)NB * NO * NHW;
    int c = blockIdx.x; int tid = threadIdx.x;
    __shared__ float ssum[256], ssq[256];
    float s = 0.f, sq = 0.f;
    for (int b = 0; b < NB; b++) {
        size_t base = (size_t)(b * 128 + c) * NHW;
        const float4* p0 = (const float4*)(g_out1s + base);
        const float4* p1 = (const float4*)(g_out1s + N + base);
        const float4* p2 = (const float4*)(g_out1s + 2 * N + base);
        const float4* p3 = (const float4*)(g_out1s + 3 * N + base);
        float4* po = (float4*)(g_out1 + base);
        for (int i = tid; i < 1024; i += 256) {
            float4 a = p0[i], bq = p1[i], cq = p2[i], dq = p3[i];
            float4 v = make_float4(a.x + bq.x + cq.x + dq.x, a.y + bq.y + cq.y + dq.y,
                                   a.z + bq.z + cq.z + dq.z, a.w + bq.w + cq.w + dq.w);
            po[i] = v;
            s  += v.x + v.y + v.z + v.w;
            sq += v.x * v.x + v.y * v.y + v.z * v.z + v.w * v.w;
        }
    }
    ssum[tid] = s; ssq[tid] = sq;
    __syncthreads();
    for (int st = 128; st; st >>= 1) {
        if (tid < st) { ssum[tid] += ssum[tid + st]; ssq[tid] += ssq[tid + st]; }
        __syncthreads();
    }
    if (tid == 0) {
        float m  = ssum[0] * (1.f / 16384.f);
        float vv = ssq[0]  * (1.f / 16384.f) - m * m;
        float sc = gamma[c] * rsqrtf(vv + 1e-5f);
        g_scale1[c] = sc;
        g_shift1[c] = beta[c] - m * sc;
    }
}

// -------- K4: conv3x3 (128->128), BN1+ReLU at load, quarter ci x co-half x h-pair. grid 1024 --------
__global__ __launch_bounds__(256) void k_conv2() {
    int quarter = blockIdx.x >> 8;
    int rem = blockIdx.x & 255;
    int cohalf = rem >> 7;
    int rem2 = rem & 127;
    int b = rem2 >> 5; int hp = rem2 & 31; int h0 = hp * 2;
    int tid = threadIdx.x; int w = tid & 63; int q = tid >> 6;
    float* outbuf = g_out2s + (size_t)quarter * (NB * NO * NHW);
    int co_base = cohalf * 64 + q * 16;

    __shared__ float sx[8 * 4 * 66];
    __shared__ float sw[8 * 9 * 64];

    unsigned long long accp[2][8];
#pragma unroll
    for (int r = 0; r < 2; r++)
#pragma unroll
        for (int p = 0; p < 8; p++) accp[r][p] = 0ull;

    for (int ch = 0; ch < 4; ch++) {
        int ci0 = quarter * 32 + ch * 8;
        __syncthreads();
        float4* sw4 = (float4*)sw;
        for (int i = tid; i < 1152; i += 256) {
            int a = i >> 4; int j = i & 15;
            sw4[i] = *(const float4*)(g_wT2 + (size_t)(ci0 * 9 + a) * 128 + cohalf * 64 + j * 4);
        }
        for (int i = tid; i < 8 * 4 * 66; i += 256) {
            int ci = i / 264; int r2 = i - ci * 264; int r = r2 / 66; int wc = r2 - r * 66;
            int hh = h0 - 1 + r; int ww = wc - 1; int c = ci0 + ci;
            float v = 0.f;
            if (hh >= 0 && hh < 64 && ww >= 0 && ww < 64) {
                float raw = g_out1[((size_t)(b * 128 + c) * 64 + hh) * 64 + ww];
                v = fmaxf(0.f, raw * g_scale1[c] + g_shift1[c]);
            }
            sx[i] = v;
        }
        __syncthreads();

        for (int ci = 0; ci < 8; ci++) {
#pragma unroll
            for (int kk = 0; kk < 9; kk++) {
                int ky = kk / 3, kx = kk % 3;
                float x0 = sx[ci * 264 + ky * 66 + w + kx];
                float x1 = sx[ci * 264 + (ky + 1) * 66 + w + kx];
                unsigned long long xb0 = pack2b(x0);
                unsigned long long xb1 = pack2b(x1);
                const ulonglong2* wrow = (const ulonglong2*)&sw[(ci * 9 + kk) * 64 + q * 16];
#pragma unroll
                for (int j4 = 0; j4 < 4; j4++) {
                    ulonglong2 wv = wrow[j4];
                    FFMA2(accp[0][2 * j4],     wv.x, xb0);
                    FFMA2(accp[0][2 * j4 + 1], wv.y, xb0);
                    FFMA2(accp[1][2 * j4],     wv.x, xb1);
                    FFMA2(accp[1][2 * j4 + 1], wv.y, xb1);
                }
            }
        }
    }

#pragma unroll
    for (int r = 0; r < 2; r++) {
        int h = h0 + r;
#pragma unroll
        for (int p = 0; p < 8; p++) {
            float2 f2 = unpack2(accp[r][p]);
            int co = co_base + 2 * p;
            outbuf[((size_t)(b * 128 + co) * 64 + h) * 64 + w]     = f2.x;
            outbuf[((size_t)(b * 128 + co + 1) * 64 + h) * 64 + w] = f2.y;
        }
    }
}

// -------- K5: combine 4 conv2 partials + BN2 stats + fold --------
__global__ __launch_bounds__(256) void k_bn2(const float* __restrict__ gamma,
                                             const float* __restrict__ beta) {
    const size_t N = (size_t)NB * NO * NHW;
    int c = blockIdx.x; int tid = threadIdx.x;
    __shared__ float ssum[256], ssq[256];
    float s = 0.f, sq = 0.f;
    for (int b = 0; b < NB; b++) {
        size_t base = (size_t)(b * 128 + c) * NHW;
        const float4* p0 = (const float4*)(g_out2s + base);
        const float4* p1 = (const float4*)(g_out2s + N + base);
        const float4* p2 = (const float4*)(g_out2s + 2 * N + base);
        const float4* p3 = (const float4*)(g_out2s + 3 * N + base);
        float4* po = (float4*)(g_out2 + base);
        for (int i = tid; i < 1024; i += 256) {
            float4 a = p0[i], bq = p1[i], cq = p2[i], dq = p3[i];
            float4 v = make_float4(a.x + bq.x + cq.x + dq.x, a.y + bq.y + cq.y + dq.y,
                                   a.z + bq.z + cq.z + dq.z, a.w + bq.w + cq.w + dq.w);
            po[i] = v;
            s  += v.x + v.y + v.z + v.w;
            sq += v.x * v.x + v.y * v.y + v.z * v.z + v.w * v.w;
        }
    }
    ssum[tid] = s; ssq[tid] = sq;
    __syncthreads();
    for (int st = 128; st; st >>= 1) {
        if (tid < st) { ssum[tid] += ssum[tid + st]; ssq[tid] += ssq[tid + st]; }
        __syncthreads();
    }
    if (tid == 0) {
        float m  = ssum[0] * (1.f / 16384.f);
        float vv = ssq[0]  * (1.f / 16384.f) - m * m;
        float sc = gamma[c] * rsqrtf(vv + 1e-5f);
        g_scale2[c] = sc;
        g_shift2[c] = beta[c] - m * sc;
    }
}

// -------- K6: final BN2 + ReLU elementwise into d_out --------
__global__ void k_final(float* __restrict__ out) {
    int idx = blockIdx.x * 256 + threadIdx.x;
    const float4* in4 = (const float4*)g_out2;
    float4 v = in4[idx];
    int c = (idx >> 10) & 127;
    float sc = g_scale2[c], sh = g_shift2[c];
    float4 r;
    r.x = fmaxf(0.f, v.x * sc + sh);
    r.y = fmaxf(0.f, v.y * sc + sh);
    r.z = fmaxf(0.f, v.z * sc + sh);
    r.w = fmaxf(0.f, v.w * sc + sh);
    ((float4*)out)[idx] = r;
}

// -------- host launcher (graph-capturable) --------
extern "C" void kernel_launch(void* const* d_in, const int* in_sizes, int n_in,
                              void* d_out, int out_size) {
    const float* input_v = (const float*)d_in[0];
    const float* input_i = (const float*)d_in[1];
    const float* off_w   = (const float*)d_in[2];
    const float* off_b   = (const float*)d_in[3];
    const float* dconv_w = (const float*)d_in[4];
    const float* bn1_g   = (const float*)d_in[5];
    const float* bn1_b   = (const float*)d_in[6];
    const float* conv2_w = (const float*)d_in[7];
    const float* bn2_g   = (const float*)d_in[8];
    const float* bn2_b   = (const float*)d_in[9];
    float* out = (float*)d_out;

    k_prep<<<3238, 256>>>(dconv_w, off_w, conv2_w, input_v, input_i);
    k_offconv<<<512, 256>>>(input_v, input_i);
    k_offpost<<<3456, 256>>>(off_b);
    k_deform<<<1024, 256>>>();
    k_bn1<<<128, 256>>>(bn1_g, bn1_b);
    k_conv2<<<1024, 256>>>();
    k_bn2<<<128, 256>>>(bn2_g, bn2_b);
    k_final<<<2048, 256>>>(out);
}